// round 13
// baseline (speedup 1.0000x reference)
#include <cuda_runtime.h>
#include <cuda_bf16.h>
#include <math.h>
#include <stdint.h>

#define N_NODES 4096
#define T_STEPS 365
#define D_IN    16
#define H_DIM   256
#define P_OUT   2
#define NB      128
#define NT      256

#if defined(__CUDA_ARCH__) && (defined(__CUDA_ARCH_FEAT_SM103_ALL) || defined(__CUDA_ARCH_FEAT_SM100_ALL))
#define HAS_TC 1
#else
#define HAS_TC 0
#endif

#define KC 64
#define NSTAGE 3
#define STAGE_BYTES 65536          // AHI 16K | ALO 16K | BHI 16K (2 halves) | BLO 16K
#define OFF_AHI 0
#define OFF_ALO 16384
#define OFF_BHI 32768
#define OFF_BLO 49152
#define SMEM_DYN (1024 + 1024 + NSTAGE * STAGE_BYTES)

typedef __nv_bfloat16 bf16;

// ---------------- device scratch (TC path) ----------------
__device__ __align__(128) bf16 g_hhi[2 * N_NODES * H_DIM];
__device__ __align__(128) bf16 g_hlo[2 * N_NODES * H_DIM];
__device__ __align__(128) bf16 g_chi[2 * N_NODES * H_DIM];
__device__ __align__(128) bf16 g_clo[2 * N_NODES * H_DIM];
__device__ __align__(128) bf16 g_HGhi[N_NODES * 2 * H_DIM];
__device__ __align__(128) bf16 g_HGlo[N_NODES * 2 * H_DIM];
__device__ __align__(128) bf16 g_hcurhi[N_NODES * H_DIM];
__device__ __align__(128) bf16 g_hcurlo[N_NODES * H_DIM];
__device__ __align__(128) bf16 g_ccurhi[N_NODES * H_DIM];
__device__ __align__(128) bf16 g_ccurlo[N_NODES * H_DIM];
__device__ __align__(128) bf16 g_GhiT[2 * H_DIM * N_NODES];
__device__ __align__(128) bf16 g_GloT[2 * H_DIM * N_NODES];
__device__ __align__(128) bf16 g_Ahi[(size_t)N_NODES * N_NODES];
__device__ __align__(128) bf16 g_Alo[(size_t)N_NODES * N_NODES];
__device__ __align__(128) bf16 g_xhi[(size_t)N_NODES * T_STEPS * D_IN];
__device__ __align__(128) bf16 g_xlo[(size_t)N_NODES * T_STEPS * D_IN];
__device__ __align__(128) bf16 g_rkThi[4 * H_DIM * H_DIM], g_rkTlo[4 * H_DIM * H_DIM];
__device__ __align__(128) bf16 g_kThi [4 * H_DIM * D_IN],  g_kTlo [4 * H_DIM * D_IN];
__device__ __align__(128) bf16 g_WghThi[H_DIM * H_DIM], g_WghTlo[H_DIM * H_DIM];
__device__ __align__(128) bf16 g_WgcThi[H_DIM * H_DIM], g_WgcTlo[H_DIM * H_DIM];
__device__ __align__(128) bf16 g_WhcThi[H_DIM * H_DIM], g_WhcTlo[H_DIM * H_DIM];
__device__ __align__(128) bf16 g_WhpThi[H_DIM * H_DIM], g_WhpTlo[H_DIM * H_DIM];
__device__ __align__(128) bf16 g_WccThi[H_DIM * H_DIM], g_WccTlo[H_DIM * H_DIM];
__device__ __align__(128) bf16 g_WcpThi[H_DIM * H_DIM], g_WcpTlo[H_DIM * H_DIM];
__device__ float g_z[N_NODES * 4 * H_DIM];
// fallback (fp32) scratch
__device__ float g_h[2 * N_NODES * H_DIM];
__device__ float g_c[2 * N_NODES * H_DIM];
__device__ float g_G [N_NODES * 2 * H_DIM];
__device__ float g_HG[N_NODES * 2 * H_DIM];
__device__ float g_hcur[N_NODES * H_DIM];
__device__ float g_ccur[N_NODES * H_DIM];

// ---------------- helpers ----------------
__device__ __forceinline__ uint32_t smem_u32(const void* p) {
    uint32_t a;
    asm("{ .reg .u64 t; cvta.to.shared.u64 t, %1; cvt.u32.u64 %0, t; }" : "=r"(a) : "l"(p));
    return a;
}
#define SW128(o) ((o) ^ (((o) >> 3) & 0x70))
__device__ __forceinline__ float sigmoidf_(float x) { return 1.f / (1.f + expf(-x)); }
__device__ __forceinline__ void bsplit(float v, bf16* hi, bf16* lo) {
    bf16 h = __float2bfloat16(v);
    *hi = h;
    *lo = __float2bfloat16(v - __bfloat162float(h));
}

#if HAS_TC
__device__ __forceinline__ uint32_t elect_one() {
    uint32_t p;
    asm volatile("{ .reg .pred p; elect.sync _|p, 0xFFFFFFFF; selp.b32 %0, 1, 0, p; }" : "=r"(p));
    return p;
}
#define CP_ASYNC16(dst, src) \
    asm volatile("cp.async.cg.shared.global [%0], [%1], 16;" :: "r"(dst), "l"(src) : "memory")
// .noinc: the async arrive CONSUMES one expected arrival (init count must
// include it). Without .noinc the op is net-zero on the phase -> deadlock.
#define CP_MBAR_ARRIVE(a) \
    asm volatile("cp.async.mbarrier.arrive.noinc.shared::cta.b64 [%0];" :: "r"(a) : "memory")
#define MBAR_INIT(a, c) \
    asm volatile("mbarrier.init.shared.b64 [%0], %1;" :: "r"(a), "r"(c) : "memory")
#define MBAR_WAIT(a, par) do { \
    uint32_t _m = (a), _p = (par), _d; \
    asm volatile("{ .reg .pred p; mbarrier.try_wait.parity.acquire.cta.shared::cta.b64 p, [%1], %2; selp.b32 %0,1,0,p; }" \
        : "=r"(_d) : "r"(_m), "r"(_p) : "memory"); \
    if (!_d) { \
        asm volatile("{ .reg .pred P1; WL_%=: mbarrier.try_wait.parity.acquire.cta.shared::cta.b64 P1, [%0], %1, 0x989680; @P1 bra.uni WD_%=; bra.uni WL_%=; WD_%=: }" \
            :: "r"(_m), "r"(_p) : "memory"); \
    } } while (0)
#define TC_ALLOC(sp, n)   asm volatile("tcgen05.alloc.cta_group::1.sync.aligned.shared::cta.b32 [%0], %1;" :: "r"(sp), "r"(n) : "memory")
#define TC_DEALLOC(t, n)  asm volatile("tcgen05.dealloc.cta_group::1.sync.aligned.b32 %0, %1;" :: "r"(t), "r"(n))
#define TC_COMMIT(mb)     asm volatile("tcgen05.commit.cta_group::1.mbarrier::arrive::one.shared::cluster.b64 [%0];" :: "r"(mb) : "memory")
#define TC_FENCE_AFTER()  asm volatile("tcgen05.fence::after_thread_sync;" ::: "memory")
#define TC_FENCE_BEFORE() asm volatile("tcgen05.fence::before_thread_sync;" ::: "memory")
#define TC_WAIT_LD()      asm volatile("tcgen05.wait::ld.sync.aligned;" ::: "memory")
#define FENCE_ASYNC()     asm volatile("fence.proxy.async.shared::cta;" ::: "memory")

static __device__ __forceinline__ uint64_t make_desc_k(uint32_t addr) {
    return ((uint64_t)2 << 61) | ((uint64_t)1 << 46) | ((uint64_t)64 << 32) |
           ((uint64_t)1 << 16) | ((uint64_t)(addr >> 4) & 0x3FFF);
}
#define MMA_IDESC ((1u<<4)|(1u<<7)|(1u<<10)|(8u<<17)|(8u<<24))
__device__ __forceinline__ void mma_ss(uint32_t d, uint64_t ad, uint64_t bd, bool acc) {
    uint32_t en = acc ? 1u : 0u;
    asm volatile(
        "{ .reg .pred p; setp.ne.u32 p, %5, 0;\n\t"
        "tcgen05.mma.cta_group::1.kind::f16 [%0], %1, %2, %3, {%4,%4,%4,%4}, p; }"
        :: "r"(d), "l"(ad), "l"(bd), "r"(MMA_IDESC), "r"(0u), "r"(en) : "memory");
}
#define TC_LD_X32(r, ta) \
    asm volatile("tcgen05.ld.sync.aligned.32x32b.x32.b32 " \
        "{%0,%1,%2,%3,%4,%5,%6,%7,%8,%9,%10,%11,%12,%13,%14,%15," \
        "%16,%17,%18,%19,%20,%21,%22,%23,%24,%25,%26,%27,%28,%29,%30,%31}, [%32];" \
        : "=r"((r)[0]),"=r"((r)[1]),"=r"((r)[2]),"=r"((r)[3]),"=r"((r)[4]),"=r"((r)[5]),"=r"((r)[6]),"=r"((r)[7]), \
          "=r"((r)[8]),"=r"((r)[9]),"=r"((r)[10]),"=r"((r)[11]),"=r"((r)[12]),"=r"((r)[13]),"=r"((r)[14]),"=r"((r)[15]), \
          "=r"((r)[16]),"=r"((r)[17]),"=r"((r)[18]),"=r"((r)[19]),"=r"((r)[20]),"=r"((r)[21]),"=r"((r)[22]),"=r"((r)[23]), \
          "=r"((r)[24]),"=r"((r)[25]),"=r"((r)[26]),"=r"((r)[27]),"=r"((r)[28]),"=r"((r)[29]),"=r"((r)[30]),"=r"((r)[31]) \
        : "r"(ta))

struct Seg {
    const bf16* Ahi; const bf16* Alo; int lda;
    const bf16* Bhi; const bf16* Blo; int ldb;
    int nchunk;
    int ksec;          // valid 16B sections per chunk row (8 or 2)
};

__device__ __forceinline__ void seg_of(const Seg* segs, int c, int& si, int& kc) {
    if (c < segs[0].nchunk) { si = 0; kc = c * KC; }
    else                    { si = 1; kc = (c - segs[0].nchunk) * KC; }
}

__device__ __forceinline__ void load_chunk(uint32_t st, const Seg& sg, int kc, int tid) {
    const int ksec = sg.ksec;
#pragma unroll 4
    for (int q = tid; q < 1024; q += NT) {
        int row = q >> 3, sc = q & 7;
        if (sc < ksec) {
            uint32_t d = SW128((uint32_t)(row * 128 + sc * 16));
            CP_ASYNC16(st + OFF_AHI + d, sg.Ahi + (size_t)row * sg.lda + kc + sc * 8);
            CP_ASYNC16(st + OFF_ALO + d, sg.Alo + (size_t)row * sg.lda + kc + sc * 8);
            uint32_t d2 = SW128((uint32_t)((row & 63) * 128 + sc * 16)) + (row >> 6) * 8192;
            CP_ASYNC16(st + OFF_BHI + d2, sg.Bhi + (size_t)row * sg.ldb + kc + sc * 8);
            CP_ASYNC16(st + OFF_BLO + d2, sg.Blo + (size_t)row * sg.ldb + kc + sc * 8);
        }
    }
}

// Decoupled 3-stage pipeline (no __syncthreads / no cp.async.wait in the loop):
//  - every thread: wait mma mbar of chunk cc-1 (stage-free guard), issue its
//    slice of chunk cc+2's loads, signal full[(cc+2)%3] via
//    cp.async.mbarrier.arrive.noinc (count = NT arrivals per chunk).
//  - elected thread additionally: wait full[s], issue MMAs, commit mma[s].
// Parity safety: a thread can only issue chunk cc+2's loads after passing the
// mma(cc-1) wait; the elected can only commit mma(cc) after full(cc) completes,
// which needs ALL threads' chunk-cc arrivals (issued after their mma(cc-3)
// wait). Commit k's block-wide wait therefore always completes before commit
// k+1 on the same mbar; same argument bounds full-mbar reuse.
__device__ __noinline__ void tc_tile_run(uint32_t ctrl, const uint32_t* stage_u,
                                         uint32_t tmem, const Seg* segs, int nseg,
                                         int* mcnt, int* fcnt, int tid, int wid,
                                         uint32_t is_e)
{
    int total = segs[0].nchunk;
    if (nseg > 1) total += segs[1].nchunk;

    // preload chunks 0,1
    for (int pre = 0; pre < 2 && pre < total; ++pre) {
        int si, kc;
        seg_of(segs, pre, si, kc);
        load_chunk(stage_u[pre], segs[si], kc, tid);
        CP_MBAR_ARRIVE(ctrl + 32 + pre * 8);
    }

    for (int cc = 0; cc < total; ++cc) {
        const int s = cc % NSTAGE;
        // stage-free guard: MMA(cc-1) complete (all threads)
        if (cc >= 1) {
            const int pw = (cc - 1) % NSTAGE;
            MBAR_WAIT(ctrl + 8 + pw * 8, mcnt[pw] & 1);
            mcnt[pw]++;
        }
        // issue chunk cc+2's loads + full arrival
        if (cc + 2 < total) {
            int si2, kc2;
            seg_of(segs, cc + 2, si2, kc2);
            const int s2 = (cc + 2) % NSTAGE;
            load_chunk(stage_u[s2], segs[si2], kc2, tid);
            CP_MBAR_ARRIVE(ctrl + 32 + s2 * 8);
        }
        // elected: wait data, run MMAs
        if (is_e) {
            MBAR_WAIT(ctrl + 32 + s * 8, fcnt[s] & 1);
            fcnt[s]++;
            FENCE_ASYNC();
            int si, kc;
            seg_of(segs, cc, si, kc);
            const int nks = segs[si].ksec >> 1;
            uint64_t aHi = make_desc_k(stage_u[s] + OFF_AHI);
            uint64_t aLo = make_desc_k(stage_u[s] + OFF_ALO);
#pragma unroll
            for (int half = 0; half < 2; half++) {
                uint32_t dD = tmem + half * 64;
                uint64_t bHi = make_desc_k(stage_u[s] + OFF_BHI + half * 8192);
                uint64_t bLo = make_desc_k(stage_u[s] + OFF_BLO + half * 8192);
                for (int ks = 0; ks < nks; ks++)
                    mma_ss(dD, aHi + ks * 2, bHi + ks * 2, !(cc == 0 && ks == 0));
                for (int ks = 0; ks < nks; ks++)
                    mma_ss(dD, aHi + ks * 2, bLo + ks * 2, true);
                for (int ks = 0; ks < nks; ks++)
                    mma_ss(dD, aLo + ks * 2, bHi + ks * 2, true);
            }
            TC_COMMIT(ctrl + 8 + s * 8);
        }
    }
    // final: all threads wait MMA(total-1)
    {
        const int pw = (total - 1) % NSTAGE;
        MBAR_WAIT(ctrl + 8 + pw * 8, mcnt[pw] & 1);
        mcnt[pw]++;
    }
    TC_FENCE_AFTER();
}
#endif // HAS_TC

// ---------------- grid barrier ----------------
__device__ unsigned g_count;
__device__ volatile unsigned g_gen;
__device__ __forceinline__ void gsync() {
    __threadfence();
    __syncthreads();
    if (threadIdx.x == 0) {
        unsigned gen = g_gen;
        if (atomicAdd(&g_count, 1u) == (unsigned)NB - 1u) {
            g_count = 0;
            __threadfence();
            g_gen = gen + 1u;
        } else {
            while (g_gen == gen) __nanosleep(64);
            __threadfence();
        }
    }
    __syncthreads();
}

// ---------------- fp32 fallback GEMM ----------------
struct SmemTiles {
    float As[8][132];
    float Bs[8][132];
};
__device__ __noinline__ void gemm_tile(
    SmemTiles* smB,
    float* __restrict__ C, int ldc,
    const float* __restrict__ A1, int lda1,
    const float* __restrict__ B1, int ldb1, int K1,
    const float* __restrict__ A2, int lda2,
    const float* __restrict__ B2, int ldb2, int K2,
    const float* __restrict__ bias, int m0, int n0, int act)
{
    const int tid = threadIdx.x;
    const int tx = tid & 15, ty = tid >> 4;
    const int arow = tid >> 1, acol = (tid & 1) * 4;
    const int brow = tid >> 5, bcol = (tid & 31) * 4;
    float acc[8][8];
#pragma unroll
    for (int i = 0; i < 8; i++)
#pragma unroll
        for (int j = 0; j < 8; j++) acc[i][j] = 0.f;
    int buf = 0;
    const int npass = A2 ? 2 : 1;
    for (int pass = 0; pass < npass; ++pass) {
        const float* A = pass ? A2 : A1;
        const float* B = pass ? B2 : B1;
        const int lda = pass ? lda2 : lda1;
        const int ldb = pass ? ldb2 : ldb1;
        const int K   = pass ? K2  : K1;
        float4 av = __ldcg((const float4*)(A + (size_t)(m0 + arow) * lda + acol));
        float4 bv = __ldcg((const float4*)(B + (size_t)(brow) * ldb + n0 + bcol));
        for (int k0 = 0; k0 < K; k0 += 8) {
            SmemTiles* sm = &smB[buf];
            sm->As[acol + 0][arow] = av.x;
            sm->As[acol + 1][arow] = av.y;
            sm->As[acol + 2][arow] = av.z;
            sm->As[acol + 3][arow] = av.w;
            *(float4*)&sm->Bs[brow][bcol] = bv;
            __syncthreads();
            if (k0 + 8 < K) {
                av = __ldcg((const float4*)(A + (size_t)(m0 + arow) * lda + k0 + 8 + acol));
                bv = __ldcg((const float4*)(B + (size_t)(k0 + 8 + brow) * ldb + n0 + bcol));
            }
#pragma unroll
            for (int k = 0; k < 8; k++) {
                float4 a0 = *(const float4*)&sm->As[k][ty * 8];
                float4 a1 = *(const float4*)&sm->As[k][ty * 8 + 4];
                float4 b0 = *(const float4*)&sm->Bs[k][tx * 8];
                float4 b1 = *(const float4*)&sm->Bs[k][tx * 8 + 4];
                float ar[8] = {a0.x, a0.y, a0.z, a0.w, a1.x, a1.y, a1.z, a1.w};
                float br[8] = {b0.x, b0.y, b0.z, b0.w, b1.x, b1.y, b1.z, b1.w};
#pragma unroll
                for (int i = 0; i < 8; i++)
#pragma unroll
                    for (int j = 0; j < 8; j++)
                        acc[i][j] = fmaf(ar[i], br[j], acc[i][j]);
            }
            buf ^= 1;
        }
    }
    float bv8[8];
#pragma unroll
    for (int j = 0; j < 8; j++) bv8[j] = bias ? bias[n0 + tx * 8 + j] : 0.f;
#pragma unroll
    for (int i = 0; i < 8; i++) {
        float r[8];
#pragma unroll
        for (int j = 0; j < 8; j++) {
            float v = acc[i][j] + bv8[j];
            if (act == 1)      v = tanhf(v);
            else if (act == 2) v = sigmoidf_(v);
            r[j] = v;
        }
        float* cp = C + (size_t)(m0 + ty * 8 + i) * ldc + n0 + tx * 8;
        *(float4*)(cp)     = make_float4(r[0], r[1], r[2], r[3]);
        *(float4*)(cp + 4) = make_float4(r[4], r[5], r[6], r[7]);
    }
}

// ---------------- persistent kernel ----------------
__global__ void __launch_bounds__(NT, 1) rgcn_persistent(
    const float* __restrict__ inputs, const float* __restrict__ A,
    const float* __restrict__ kernelW, const float* __restrict__ rkernel,
    const float* __restrict__ lstm_b,
    const float* __restrict__ W_gh, const float* __restrict__ b_gh,
    const float* __restrict__ W_gc, const float* __restrict__ b_gc,
    const float* __restrict__ W_hc, const float* __restrict__ W_hp,
    const float* __restrict__ b_h,
    const float* __restrict__ W_cc, const float* __restrict__ W_cp,
    const float* __restrict__ b_c,
    const float* __restrict__ W_out, const float* __restrict__ b_out,
    float* __restrict__ out)
{
    extern __shared__ char smraw[];
    const int bid = blockIdx.x;
    const int tid = threadIdx.x;
    const int wid = tid >> 5;
    const int lid = tid & 31;
    const size_t stateN = (size_t)N_NODES * H_DIM;
    const int gt = bid * NT + tid, gs = NB * NT;

    uint32_t sb_raw = smem_u32(smraw);
    uint32_t sb = (sb_raw + 1023u) & ~1023u;
    char* smb = smraw + (sb - sb_raw);
    SmemTiles* smB = (SmemTiles*)(smb + 1024);

#if HAS_TC
    uint32_t ctrl = sb;   // [0] tmem ptr, [8,16,24] mma mbars, [32,40,48] full mbars
    uint32_t stage_u[NSTAGE] = {sb + 1024, sb + 1024 + STAGE_BYTES,
                                sb + 1024 + 2 * STAGE_BYTES};
    int mcnt[NSTAGE] = {0, 0, 0};
    int fcnt[NSTAGE] = {0, 0, 0};
    if (tid == 0) {
        MBAR_INIT(ctrl + 8, 1);  MBAR_INIT(ctrl + 16, 1); MBAR_INIT(ctrl + 24, 1);
        MBAR_INIT(ctrl + 32, NT); MBAR_INIT(ctrl + 40, NT); MBAR_INIT(ctrl + 48, NT);
    }
    if (wid == 0) TC_ALLOC(ctrl, 512);
    __syncthreads();
    uint32_t tmem_base;
    asm volatile("ld.shared.b32 %0, [%1];" : "=r"(tmem_base) : "r"(ctrl));
    uint32_t is_e = (wid == 0) ? elect_one() : 0u;

    // ---- one-time init ----
    for (int i = gt; i < (int)stateN; i += gs) {
        g_hhi[i] = __float2bfloat16(0.f); g_hlo[i] = __float2bfloat16(0.f);
        g_chi[i] = __float2bfloat16(0.f); g_clo[i] = __float2bfloat16(0.f);
    }
    for (size_t i = (size_t)gt; i < (size_t)N_NODES * N_NODES; i += (size_t)gs)
        bsplit(A[i], &g_Ahi[i], &g_Alo[i]);
    for (size_t i = (size_t)gt; i < (size_t)N_NODES * T_STEPS * D_IN; i += (size_t)gs)
        bsplit(inputs[i], &g_xhi[i], &g_xlo[i]);
    for (int i = gt; i < 4 * H_DIM * H_DIM; i += gs) {
        int n = i >> 8, k = i & 255;
        bsplit(rkernel[k * (4 * H_DIM) + n], &g_rkThi[i], &g_rkTlo[i]);
    }
    for (int i = gt; i < 4 * H_DIM * D_IN; i += gs) {
        int n = i >> 4, k = i & 15;
        bsplit(kernelW[k * (4 * H_DIM) + n], &g_kThi[i], &g_kTlo[i]);
    }
    for (int i = gt; i < H_DIM * H_DIM; i += gs) {
        int n = i >> 8, k = i & 255;
        bsplit(W_gh[k * H_DIM + n], &g_WghThi[i], &g_WghTlo[i]);
        bsplit(W_gc[k * H_DIM + n], &g_WgcThi[i], &g_WgcTlo[i]);
        bsplit(W_hc[k * H_DIM + n], &g_WhcThi[i], &g_WhcTlo[i]);
        bsplit(W_hp[k * H_DIM + n], &g_WhpThi[i], &g_WhpTlo[i]);
        bsplit(W_cc[k * H_DIM + n], &g_WccThi[i], &g_WccTlo[i]);
        bsplit(W_cp[k * H_DIM + n], &g_WcpThi[i], &g_WcpTlo[i]);
    }
#else
    for (int i = gt; i < (int)stateN; i += gs) { g_h[i] = 0.f; g_c[i] = 0.f; }
#endif
    gsync();

    const int m0 = (bid >> 2) * 128;
    const int n0 = (bid & 3) * 128;

    for (int t = 0; t < T_STEPS; ++t) {
        const int cur = t & 1, nxt = (t + 1) & 1;

#if HAS_TC
        const bf16* hphi = g_hhi + (size_t)cur * stateN;
        const bf16* hplo = g_hlo + (size_t)cur * stateN;
        const bf16* cphi = g_chi + (size_t)cur * stateN;
        const bf16* cplo = g_clo + (size_t)cur * stateN;

        if (t > 0) {
            int warp = bid * (NT / 32) + wid;
            for (int r = warp; r < N_NODES; r += NB * (NT / 32)) {
                float s0 = 0.f, s1 = 0.f;
#pragma unroll
                for (int j = 0; j < 8; j++) {
                    int k = lid + 32 * j;
                    size_t ix = (size_t)r * H_DIM + k;
                    float hv = __bfloat162float(__ldcg(hphi + ix)) +
                               __bfloat162float(__ldcg(hplo + ix));
                    s0 = fmaf(hv, W_out[2 * k + 0], s0);
                    s1 = fmaf(hv, W_out[2 * k + 1], s1);
                }
#pragma unroll
                for (int o = 16; o > 0; o >>= 1) {
                    s0 += __shfl_down_sync(0xffffffffu, s0, o);
                    s1 += __shfl_down_sync(0xffffffffu, s1, o);
                }
                if (lid == 0) {
                    size_t base = (size_t)r * T_STEPS * P_OUT + (size_t)(t - 1) * P_OUT;
                    out[base + 0] = s0 + b_out[0];
                    out[base + 1] = s1 + b_out[1];
                }
            }
        }

        // ---- PHASE A: G tile -> G^T split ----
        {
            const bool isH = (n0 < 256);
            Seg sg[1];
            sg[0].Ahi = (isH ? hphi : cphi) + (size_t)m0 * H_DIM;
            sg[0].Alo = (isH ? hplo : cplo) + (size_t)m0 * H_DIM;
            sg[0].lda = H_DIM;
            sg[0].Bhi = (isH ? g_WghThi : g_WgcThi) + (size_t)(n0 & 255) * H_DIM;
            sg[0].Blo = (isH ? g_WghTlo : g_WgcTlo) + (size_t)(n0 & 255) * H_DIM;
            sg[0].ldb = H_DIM;
            sg[0].nchunk = 4; sg[0].ksec = 8;
            tc_tile_run(ctrl, stage_u, tmem_base, sg, 1, mcnt, fcnt, tid, wid, is_e);
            const float* gb = isH ? b_gh : b_gc;
            if (wid < 4) {
                int row = m0 + wid * 32 + lid;
                uint32_t rg[32];
#pragma unroll 1
                for (int cb = 0; cb < 128; cb += 32) {
                    TC_LD_X32(rg, tmem_base + cb);
                    TC_WAIT_LD();
#pragma unroll
                    for (int jj = 0; jj < 32; jj++) {
                        int gcol = n0 + cb + jj;
                        float v = __uint_as_float(rg[jj]) + gb[gcol & 255];
                        bf16 hi, lo; bsplit(v, &hi, &lo);
                        g_GhiT[(size_t)gcol * N_NODES + row] = hi;
                        g_GloT[(size_t)gcol * N_NODES + row] = lo;
                    }
                }
                TC_FENCE_BEFORE();
            }
            __syncthreads();
        }
        // z tiles (2 per CTA)
#pragma unroll 1
        for (int zi = 0; zi < 2; zi++) {
            int zt = bid + zi * 128;
            int mz = (zt >> 3) * 128, nz = (zt & 7) * 128;
            Seg sg[2];
            sg[0].Ahi = g_xhi + (size_t)mz * (T_STEPS * D_IN) + (size_t)t * D_IN;
            sg[0].Alo = g_xlo + (size_t)mz * (T_STEPS * D_IN) + (size_t)t * D_IN;
            sg[0].lda = T_STEPS * D_IN;
            sg[0].Bhi = g_kThi + (size_t)nz * D_IN;
            sg[0].Blo = g_kTlo + (size_t)nz * D_IN;
            sg[0].ldb = D_IN;
            sg[0].nchunk = 1; sg[0].ksec = 2;
            sg[1].Ahi = hphi + (size_t)mz * H_DIM;
            sg[1].Alo = hplo + (size_t)mz * H_DIM;
            sg[1].lda = H_DIM;
            sg[1].Bhi = g_rkThi + (size_t)nz * H_DIM;
            sg[1].Blo = g_rkTlo + (size_t)nz * H_DIM;
            sg[1].ldb = H_DIM;
            sg[1].nchunk = 4; sg[1].ksec = 8;
            tc_tile_run(ctrl, stage_u, tmem_base, sg, 2, mcnt, fcnt, tid, wid, is_e);
            if (wid < 4) {
                int row = mz + wid * 32 + lid;
                uint32_t rg[32];
#pragma unroll 1
                for (int cb = 0; cb < 128; cb += 32) {
                    TC_LD_X32(rg, tmem_base + cb);
                    TC_WAIT_LD();
#pragma unroll
                    for (int jj = 0; jj < 32; jj++) {
                        int zc = nz + cb + jj;
                        g_z[(size_t)row * (4 * H_DIM) + zc] =
                            __uint_as_float(rg[jj]) + lstm_b[zc];
                    }
                }
                TC_FENCE_BEFORE();
            }
            __syncthreads();
        }
        gsync();

        // ---- PHASE B ----
        for (int idx = gt; idx < N_NODES * H_DIM; idx += gs) {
            int n = idx >> 8, hh = idx & 255;
            const float* zr = g_z + (size_t)n * (4 * H_DIM);
            float zi = __ldcg(zr + hh);
            float zf = __ldcg(zr + H_DIM + hh);
            float zg = __ldcg(zr + 2 * H_DIM + hh);
            float zo = __ldcg(zr + 3 * H_DIM + hh);
            float cp = __bfloat162float(__ldcg(cphi + idx)) +
                       __bfloat162float(__ldcg(cplo + idx));
            float c = sigmoidf_(zf) * cp + sigmoidf_(zi) * tanhf(zg);
            bsplit(c, &g_ccurhi[idx], &g_ccurlo[idx]);
            bsplit(sigmoidf_(zo) * tanhf(c), &g_hcurhi[idx], &g_hcurlo[idx]);
        }
        __syncthreads();
        {
            Seg sg[1];
            sg[0].Ahi = g_Ahi + (size_t)m0 * N_NODES;
            sg[0].Alo = g_Alo + (size_t)m0 * N_NODES;
            sg[0].lda = N_NODES;
            sg[0].Bhi = g_GhiT + (size_t)n0 * N_NODES;
            sg[0].Blo = g_GloT + (size_t)n0 * N_NODES;
            sg[0].ldb = N_NODES;
            sg[0].nchunk = 64; sg[0].ksec = 8;
            tc_tile_run(ctrl, stage_u, tmem_base, sg, 1, mcnt, fcnt, tid, wid, is_e);
            if (wid < 4) {
                int row = m0 + wid * 32 + lid;
                uint32_t rg[32];
#pragma unroll 1
                for (int cb = 0; cb < 128; cb += 32) {
                    TC_LD_X32(rg, tmem_base + cb);
                    TC_WAIT_LD();
#pragma unroll
                    for (int jj = 0; jj < 32; jj++) {
                        float v = tanhf(__uint_as_float(rg[jj]));
                        bf16 hi, lo; bsplit(v, &hi, &lo);
                        size_t ix = (size_t)row * (2 * H_DIM) + n0 + cb + jj;
                        g_HGhi[ix] = hi; g_HGlo[ix] = lo;
                    }
                }
                TC_FENCE_BEFORE();
            }
            __syncthreads();
        }
        gsync();

        // ---- PHASE C ----
        {
            const bool isH = (bid < 64);
            int ci = isH ? bid : bid - 64;
            int mc = (ci >> 1) * 128, nc = (ci & 1) * 128;
            Seg sg[2];
            sg[0].Ahi = (isH ? g_hcurhi : g_ccurhi) + (size_t)mc * H_DIM;
            sg[0].Alo = (isH ? g_hcurlo : g_ccurlo) + (size_t)mc * H_DIM;
            sg[0].lda = H_DIM;
            sg[0].Bhi = (isH ? g_WhcThi : g_WccThi) + (size_t)nc * H_DIM;
            sg[0].Blo = (isH ? g_WhcTlo : g_WccTlo) + (size_t)nc * H_DIM;
            sg[0].ldb = H_DIM;
            sg[0].nchunk = 4; sg[0].ksec = 8;
            sg[1].Ahi = g_HGhi + (size_t)mc * (2 * H_DIM) + (isH ? 0 : H_DIM);
            sg[1].Alo = g_HGlo + (size_t)mc * (2 * H_DIM) + (isH ? 0 : H_DIM);
            sg[1].lda = 2 * H_DIM;
            sg[1].Bhi = (isH ? g_WhpThi : g_WcpThi) + (size_t)nc * H_DIM;
            sg[1].Blo = (isH ? g_WhpTlo : g_WcpTlo) + (size_t)nc * H_DIM;
            sg[1].ldb = H_DIM;
            sg[1].nchunk = 4; sg[1].ksec = 8;
            tc_tile_run(ctrl, stage_u, tmem_base, sg, 2, mcnt, fcnt, tid, wid, is_e);
            const float* cbias = isH ? b_h : b_c;
            bf16* Sh = (isH ? g_hhi : g_chi) + (size_t)nxt * stateN;
            bf16* Sl = (isH ? g_hlo : g_clo) + (size_t)nxt * stateN;
            if (wid < 4) {
                int row = mc + wid * 32 + lid;
                uint32_t rg[32];
#pragma unroll 1
                for (int cb = 0; cb < 128; cb += 32) {
                    TC_LD_X32(rg, tmem_base + cb);
                    TC_WAIT_LD();
#pragma unroll
                    for (int jj = 0; jj < 32; jj++) {
                        int sc = nc + cb + jj;
                        float v = sigmoidf_(__uint_as_float(rg[jj]) + cbias[sc]);
                        bf16 hi, lo; bsplit(v, &hi, &lo);
                        size_t ix = (size_t)row * H_DIM + sc;
                        Sh[ix] = hi; Sl[ix] = lo;
                    }
                }
                TC_FENCE_BEFORE();
            }
            __syncthreads();
        }
        gsync();

#else   // ------------------- fp32 fallback path -------------------
        float* h_prev = g_h + (size_t)cur * stateN;
        float* c_prev = g_c + (size_t)cur * stateN;
        float* h_next = g_h + (size_t)nxt * stateN;
        float* c_next = g_c + (size_t)nxt * stateN;
        if (t > 0) {
            int warp = bid * (NT / 32) + wid;
            for (int r = warp; r < N_NODES; r += NB * (NT / 32)) {
                const float* hr = h_prev + (size_t)r * H_DIM;
                float s0 = 0.f, s1 = 0.f;
#pragma unroll
                for (int j = 0; j < 8; j++) {
                    int k = lid + 32 * j;
                    float hv = __ldcg(hr + k);
                    s0 = fmaf(hv, W_out[2 * k + 0], s0);
                    s1 = fmaf(hv, W_out[2 * k + 1], s1);
                }
#pragma unroll
                for (int o = 16; o > 0; o >>= 1) {
                    s0 += __shfl_down_sync(0xffffffffu, s0, o);
                    s1 += __shfl_down_sync(0xffffffffu, s1, o);
                }
                if (lid == 0) {
                    size_t base = (size_t)r * T_STEPS * P_OUT + (size_t)(t - 1) * P_OUT;
                    out[base + 0] = s0 + b_out[0];
                    out[base + 1] = s1 + b_out[1];
                }
            }
        }
#pragma unroll 1
        for (int tile = bid; tile < 384; tile += NB) {
            if (tile < 64) {
                int tm = (tile >> 1) * 128, tn = (tile & 1) * 128;
                gemm_tile(smB, g_G, 2 * H_DIM, h_prev, H_DIM, W_gh, H_DIM, H_DIM,
                          nullptr, 0, nullptr, 0, 0, b_gh, tm, tn, 0);
            } else if (tile < 128) {
                int tt = tile - 64;
                int tm = (tt >> 1) * 128, tn = (tt & 1) * 128;
                gemm_tile(smB, g_G + H_DIM, 2 * H_DIM, c_prev, H_DIM, W_gc, H_DIM, H_DIM,
                          nullptr, 0, nullptr, 0, 0, b_gc, tm, tn, 0);
            } else {
                int tz = tile - 128;
                int tm = (tz >> 3) * 128, tn = (tz & 7) * 128;
                gemm_tile(smB, g_z, 4 * H_DIM,
                          inputs + (size_t)t * D_IN, T_STEPS * D_IN, kernelW, 4 * H_DIM, D_IN,
                          h_prev, H_DIM, rkernel, 4 * H_DIM, H_DIM,
                          lstm_b, tm, tn, 0);
            }
        }
        gsync();
        for (int idx = gt; idx < N_NODES * H_DIM; idx += gs) {
            int n = idx >> 8, hh = idx & 255;
            const float* zr = g_z + (size_t)n * (4 * H_DIM);
            float zi = __ldcg(zr + hh);
            float zf = __ldcg(zr + H_DIM + hh);
            float zg = __ldcg(zr + 2 * H_DIM + hh);
            float zo = __ldcg(zr + 3 * H_DIM + hh);
            float c = sigmoidf_(zf) * __ldcg(c_prev + idx) + sigmoidf_(zi) * tanhf(zg);
            g_ccur[idx] = c;
            g_hcur[idx] = sigmoidf_(zo) * tanhf(c);
        }
        __syncthreads();
        gemm_tile(smB, g_HG, 2 * H_DIM, A, N_NODES, g_G, 2 * H_DIM, N_NODES,
                  nullptr, 0, nullptr, 0, 0, nullptr, m0, n0, 1);
        gsync();
        if (bid < 64) {
            int tm = (bid >> 1) * 128, tn = (bid & 1) * 128;
            gemm_tile(smB, h_next, H_DIM,
                      g_hcur, H_DIM, W_hc, H_DIM, H_DIM,
                      g_HG, 2 * H_DIM, W_hp, H_DIM, H_DIM,
                      b_h, tm, tn, 2);
        } else {
            int tt = bid - 64;
            int tm = (tt >> 1) * 128, tn = (tt & 1) * 128;
            gemm_tile(smB, c_next, H_DIM,
                      g_ccur, H_DIM, W_cc, H_DIM, H_DIM,
                      g_HG + H_DIM, 2 * H_DIM, W_cp, H_DIM, H_DIM,
                      b_c, tm, tn, 2);
        }
        gsync();
#endif
    }

    // final output row for t = T-1
    {
        int warp = bid * (NT / 32) + wid;
        const int fb = T_STEPS & 1;
        for (int r = warp; r < N_NODES; r += NB * (NT / 32)) {
            float s0 = 0.f, s1 = 0.f;
#pragma unroll
            for (int j = 0; j < 8; j++) {
                int k = lid + 32 * j;
#if HAS_TC
                size_t ix = (size_t)fb * stateN + (size_t)r * H_DIM + k;
                float hv = __bfloat162float(__ldcg(g_hhi + ix)) +
                           __bfloat162float(__ldcg(g_hlo + ix));
#else
                float hv = __ldcg(g_h + (size_t)fb * stateN + (size_t)r * H_DIM + k);
#endif
                s0 = fmaf(hv, W_out[2 * k + 0], s0);
                s1 = fmaf(hv, W_out[2 * k + 1], s1);
            }
#pragma unroll
            for (int o = 16; o > 0; o >>= 1) {
                s0 += __shfl_down_sync(0xffffffffu, s0, o);
                s1 += __shfl_down_sync(0xffffffffu, s1, o);
            }
            if (lid == 0) {
                size_t base = (size_t)r * T_STEPS * P_OUT + (size_t)(T_STEPS - 1) * P_OUT;
                out[base + 0] = s0 + b_out[0];
                out[base + 1] = s1 + b_out[1];
            }
        }
    }

#if HAS_TC
    __syncthreads();
    if (wid == 0) TC_DEALLOC(tmem_base, 512);
#endif
}

// ---------------- launch ----------------
extern "C" void kernel_launch(void* const* d_in, const int* in_sizes, int n_in,
                              void* d_out, int out_size)
{
    const float* inputs  = (const float*)d_in[0];
    const float* A       = (const float*)d_in[1];
    const float* kernelW = (const float*)d_in[2];
    const float* rkernel = (const float*)d_in[3];
    const float* lstm_b  = (const float*)d_in[4];
    const float* W_gh    = (const float*)d_in[5];
    const float* b_gh    = (const float*)d_in[6];
    const float* W_gc    = (const float*)d_in[7];
    const float* b_gc    = (const float*)d_in[8];
    const float* W_hc    = (const float*)d_in[9];
    const float* W_hp    = (const float*)d_in[10];
    const float* b_h     = (const float*)d_in[11];
    const float* W_cc    = (const float*)d_in[12];
    const float* W_cp    = (const float*)d_in[13];
    const float* b_c     = (const float*)d_in[14];
    const float* W_out   = (const float*)d_in[15];
    const float* b_out   = (const float*)d_in[16];
    float* out = (float*)d_out;

    cudaFuncSetAttribute(rgcn_persistent,
                         cudaFuncAttributeMaxDynamicSharedMemorySize, SMEM_DYN);
    rgcn_persistent<<<NB, NT, SMEM_DYN>>>(inputs, A, kernelW, rkernel, lstm_b,
                                          W_gh, b_gh, W_gc, b_gc,
                                          W_hc, W_hp, b_h, W_cc, W_cp, b_c,
                                          W_out, b_out, out);
}

// round 14
// speedup vs baseline: 1.6770x; 1.6770x over previous
#include <cuda_runtime.h>
#include <cuda_bf16.h>
#include <math.h>
#include <stdint.h>

#define N_NODES 4096
#define T_STEPS 365
#define D_IN    16
#define H_DIM   256
#define P_OUT   2
#define NB      128
#define NT      256

#if defined(__CUDA_ARCH__) && (defined(__CUDA_ARCH_FEAT_SM103_ALL) || defined(__CUDA_ARCH_FEAT_SM100_ALL))
#define HAS_TC 1
#else
#define HAS_TC 0
#endif

#define KC 64
#define NSTAGE 3
#define STAGE_BYTES 65536          // AHI 16K | ALO 16K | BHI 16K | BLO 16K
#define OFF_AHI 0
#define OFF_ALO 16384
#define OFF_BHI 32768
#define OFF_BLO 49152
#define SMEM_DYN (1024 + 1024 + NSTAGE * STAGE_BYTES)

typedef __nv_bfloat16 bf16;

// ---------------- device scratch (TC path) ----------------
__device__ __align__(128) bf16 g_hhi[2 * N_NODES * H_DIM];
__device__ __align__(128) bf16 g_hlo[2 * N_NODES * H_DIM];
__device__ __align__(128) bf16 g_chi[2 * N_NODES * H_DIM];
__device__ __align__(128) bf16 g_clo[2 * N_NODES * H_DIM];
__device__ __align__(128) bf16 g_HGhi[N_NODES * 2 * H_DIM];
__device__ __align__(128) bf16 g_HGlo[N_NODES * 2 * H_DIM];
__device__ __align__(128) bf16 g_hcurhi[N_NODES * H_DIM];
__device__ __align__(128) bf16 g_hcurlo[N_NODES * H_DIM];
__device__ __align__(128) bf16 g_ccurhi[N_NODES * H_DIM];
__device__ __align__(128) bf16 g_ccurlo[N_NODES * H_DIM];
__device__ __align__(128) bf16 g_GhiT[2 * H_DIM * N_NODES];
__device__ __align__(128) bf16 g_GloT[2 * H_DIM * N_NODES];
__device__ __align__(128) bf16 g_Ahi[(size_t)N_NODES * N_NODES];
__device__ __align__(128) bf16 g_Alo[(size_t)N_NODES * N_NODES];
__device__ __align__(128) bf16 g_xhi[(size_t)N_NODES * T_STEPS * D_IN];
__device__ __align__(128) bf16 g_xlo[(size_t)N_NODES * T_STEPS * D_IN];
__device__ __align__(128) bf16 g_rkThi[4 * H_DIM * H_DIM], g_rkTlo[4 * H_DIM * H_DIM];
__device__ __align__(128) bf16 g_kThi [4 * H_DIM * D_IN],  g_kTlo [4 * H_DIM * D_IN];
__device__ __align__(128) bf16 g_WghThi[H_DIM * H_DIM], g_WghTlo[H_DIM * H_DIM];
__device__ __align__(128) bf16 g_WgcThi[H_DIM * H_DIM], g_WgcTlo[H_DIM * H_DIM];
__device__ __align__(128) bf16 g_WhcThi[H_DIM * H_DIM], g_WhcTlo[H_DIM * H_DIM];
__device__ __align__(128) bf16 g_WhpThi[H_DIM * H_DIM], g_WhpTlo[H_DIM * H_DIM];
__device__ __align__(128) bf16 g_WccThi[H_DIM * H_DIM], g_WccTlo[H_DIM * H_DIM];
__device__ __align__(128) bf16 g_WcpThi[H_DIM * H_DIM], g_WcpTlo[H_DIM * H_DIM];
__device__ float g_z[N_NODES * 4 * H_DIM];
// fallback (fp32) scratch
__device__ float g_h[2 * N_NODES * H_DIM];
__device__ float g_c[2 * N_NODES * H_DIM];
__device__ float g_G [N_NODES * 2 * H_DIM];
__device__ float g_HG[N_NODES * 2 * H_DIM];
__device__ float g_hcur[N_NODES * H_DIM];
__device__ float g_ccur[N_NODES * H_DIM];

// ---------------- helpers ----------------
__device__ __forceinline__ uint32_t smem_u32(const void* p) {
    uint32_t a;
    asm("{ .reg .u64 t; cvta.to.shared.u64 t, %1; cvt.u32.u64 %0, t; }" : "=r"(a) : "l"(p));
    return a;
}
#define SW128(o) ((o) ^ (((o) >> 3) & 0x70))
__device__ __forceinline__ float sigmoidf_(float x) { return 1.f / (1.f + expf(-x)); }
__device__ __forceinline__ void bsplit(float v, bf16* hi, bf16* lo) {
    bf16 h = __float2bfloat16(v);
    *hi = h;
    *lo = __float2bfloat16(v - __bfloat162float(h));
}

#if HAS_TC
__device__ __forceinline__ uint32_t elect_one() {
    uint32_t p;
    asm volatile("{ .reg .pred p; elect.sync _|p, 0xFFFFFFFF; selp.b32 %0, 1, 0, p; }" : "=r"(p));
    return p;
}
#define CP_ASYNC16(dst, src) \
    asm volatile("cp.async.cg.shared.global [%0], [%1], 16;" :: "r"(dst), "l"(src) : "memory")
#define CP_COMMIT()  asm volatile("cp.async.commit_group;" ::: "memory")
#define CP_WAIT0()   asm volatile("cp.async.wait_group 0;" ::: "memory")
#define CP_WAIT1()   asm volatile("cp.async.wait_group 1;" ::: "memory")
#define MBAR_INIT(a, c) \
    asm volatile("mbarrier.init.shared.b64 [%0], %1;" :: "r"(a), "r"(c) : "memory")
#define MBAR_WAIT(a, par) do { \
    uint32_t _m = (a), _p = (par), _d; \
    asm volatile("{ .reg .pred p; mbarrier.try_wait.parity.acquire.cta.shared::cta.b64 p, [%1], %2; selp.b32 %0,1,0,p; }" \
        : "=r"(_d) : "r"(_m), "r"(_p) : "memory"); \
    if (!_d) { \
        asm volatile("{ .reg .pred P1; WL_%=: mbarrier.try_wait.parity.acquire.cta.shared::cta.b64 P1, [%0], %1, 0x989680; @P1 bra.uni WD_%=; bra.uni WL_%=; WD_%=: }" \
            :: "r"(_m), "r"(_p) : "memory"); \
    } } while (0)
#define TC_ALLOC(sp, n)   asm volatile("tcgen05.alloc.cta_group::1.sync.aligned.shared::cta.b32 [%0], %1;" :: "r"(sp), "r"(n) : "memory")
#define TC_DEALLOC(t, n)  asm volatile("tcgen05.dealloc.cta_group::1.sync.aligned.b32 %0, %1;" :: "r"(t), "r"(n))
#define TC_COMMIT(mb)     asm volatile("tcgen05.commit.cta_group::1.mbarrier::arrive::one.shared::cluster.b64 [%0];" :: "r"(mb) : "memory")
#define TC_FENCE_AFTER()  asm volatile("tcgen05.fence::after_thread_sync;" ::: "memory")
#define TC_FENCE_BEFORE() asm volatile("tcgen05.fence::before_thread_sync;" ::: "memory")
#define TC_WAIT_LD()      asm volatile("tcgen05.wait::ld.sync.aligned;" ::: "memory")
#define FENCE_ASYNC()     asm volatile("fence.proxy.async.shared::cta;" ::: "memory")

static __device__ __forceinline__ uint64_t make_desc_k(uint32_t addr) {
    return ((uint64_t)2 << 61) | ((uint64_t)1 << 46) | ((uint64_t)64 << 32) |
           ((uint64_t)1 << 16) | ((uint64_t)(addr >> 4) & 0x3FFF);
}
// kind::f16, d=f32, a=bf16, b=bf16, K-major, N=128, M=128
#define MMA_IDESC ((1u<<4)|(1u<<7)|(1u<<10)|(16u<<17)|(8u<<24))
__device__ __forceinline__ void mma_ss(uint32_t d, uint64_t ad, uint64_t bd, bool acc) {
    uint32_t en = acc ? 1u : 0u;
    asm volatile(
        "{ .reg .pred p; setp.ne.u32 p, %5, 0;\n\t"
        "tcgen05.mma.cta_group::1.kind::f16 [%0], %1, %2, %3, {%4,%4,%4,%4}, p; }"
        :: "r"(d), "l"(ad), "l"(bd), "r"(MMA_IDESC), "r"(0u), "r"(en) : "memory");
}
#define TC_LD_X32(r, ta) \
    asm volatile("tcgen05.ld.sync.aligned.32x32b.x32.b32 " \
        "{%0,%1,%2,%3,%4,%5,%6,%7,%8,%9,%10,%11,%12,%13,%14,%15," \
        "%16,%17,%18,%19,%20,%21,%22,%23,%24,%25,%26,%27,%28,%29,%30,%31}, [%32];" \
        : "=r"((r)[0]),"=r"((r)[1]),"=r"((r)[2]),"=r"((r)[3]),"=r"((r)[4]),"=r"((r)[5]),"=r"((r)[6]),"=r"((r)[7]), \
          "=r"((r)[8]),"=r"((r)[9]),"=r"((r)[10]),"=r"((r)[11]),"=r"((r)[12]),"=r"((r)[13]),"=r"((r)[14]),"=r"((r)[15]), \
          "=r"((r)[16]),"=r"((r)[17]),"=r"((r)[18]),"=r"((r)[19]),"=r"((r)[20]),"=r"((r)[21]),"=r"((r)[22]),"=r"((r)[23]), \
          "=r"((r)[24]),"=r"((r)[25]),"=r"((r)[26]),"=r"((r)[27]),"=r"((r)[28]),"=r"((r)[29]),"=r"((r)[30]),"=r"((r)[31]) \
        : "r"(ta))

struct Seg {
    const bf16* Ahi; const bf16* Alo; int lda;
    const bf16* Bhi; const bf16* Blo; int ldb;
    int nchunk;
    int ksec;          // valid 16B sections per chunk row (8 or 2)
    int use_alo;       // include Alo*Bhi term (3-term) or not (2-term)
};

__device__ __forceinline__ void seg_of(const Seg* segs, int c, int& si, int& kc) {
    if (c < segs[0].nchunk) { si = 0; kc = c * KC; }
    else                    { si = 1; kc = (c - segs[0].nchunk) * KC; }
}

__device__ __forceinline__ void load_chunk(uint32_t st, const Seg& sg, int kc, int tid) {
    const int ksec = sg.ksec;
    const int ua = sg.use_alo;
#pragma unroll 4
    for (int q = tid; q < 1024; q += NT) {
        int row = q >> 3, sc = q & 7;
        if (sc < ksec) {
            uint32_t d = SW128((uint32_t)(row * 128 + sc * 16));
            CP_ASYNC16(st + OFF_AHI + d, sg.Ahi + (size_t)row * sg.lda + kc + sc * 8);
            if (ua)
                CP_ASYNC16(st + OFF_ALO + d, sg.Alo + (size_t)row * sg.lda + kc + sc * 8);
            CP_ASYNC16(st + OFF_BHI + d, sg.Bhi + (size_t)row * sg.ldb + kc + sc * 8);
            CP_ASYNC16(st + OFF_BLO + d, sg.Blo + (size_t)row * sg.ldb + kc + sc * 8);
        }
    }
}

// 3-stage pipelined 128x128 tile (R11 skeleton). Loads run 2 chunks ahead
// (wait_group 1). Per-stage mbarriers: commit MMA(cc) -> mbar[cc%3]; that
// commit's block-wide wait happens at iter cc+1, the next commit to the same
// mbar at cc+3 (two __syncthreads in between) -> no parity phase missed.
// N=128 single-descriptor MMAs (B rows 0..127 contiguous SW128 K-major).
__device__ __noinline__ void tc_tile_run(uint32_t ctrl, const uint32_t* stage_u,
                                         uint32_t tmem, const Seg* segs, int nseg,
                                         int* mcnt, int tid, int wid)
{
    int total = segs[0].nchunk;
    if (nseg > 1) total += segs[1].nchunk;

    // preload chunks 0 and 1 (separate commit groups)
    {
        int si, kc;
        seg_of(segs, 0, si, kc);
        load_chunk(stage_u[0], segs[si], kc, tid);
        CP_COMMIT();
        if (total > 1) {
            seg_of(segs, 1, si, kc);
            load_chunk(stage_u[1], segs[si], kc, tid);
            CP_COMMIT();
        }
    }

    for (int cc = 0; cc < total; ++cc) {
        const int s = cc % NSTAGE;
        int si, kc;
        seg_of(segs, cc, si, kc);
        const int nks = segs[si].ksec >> 1;
        if (cc + 1 < total) CP_WAIT1(); else CP_WAIT0();
        __syncthreads();
        if (wid == 0) {
            FENCE_ASYNC();
            if (elect_one()) {
                uint64_t aHi = make_desc_k(stage_u[s] + OFF_AHI);
                uint64_t bHi = make_desc_k(stage_u[s] + OFF_BHI);
                uint64_t bLo = make_desc_k(stage_u[s] + OFF_BLO);
                for (int ks = 0; ks < nks; ks++)
                    mma_ss(tmem, aHi + ks * 2, bHi + ks * 2, !(cc == 0 && ks == 0));
                for (int ks = 0; ks < nks; ks++)
                    mma_ss(tmem, aHi + ks * 2, bLo + ks * 2, true);
                if (segs[si].use_alo) {
                    uint64_t aLo = make_desc_k(stage_u[s] + OFF_ALO);
                    for (int ks = 0; ks < nks; ks++)
                        mma_ss(tmem, aLo + ks * 2, bHi + ks * 2, true);
                }
                TC_COMMIT(ctrl + 8 + s * 8);
            }
        }
        // wait MMA(cc-1) on its own mbar before overwriting its stage (cc+2)%3
        if (cc >= 1) {
            const int pw = (cc - 1) % NSTAGE;
            MBAR_WAIT(ctrl + 8 + pw * 8, mcnt[pw] & 1);
            mcnt[pw]++;
        }
        if (cc + 2 < total) {
            int si2, kc2;
            seg_of(segs, cc + 2, si2, kc2);
            load_chunk(stage_u[(cc + 2) % NSTAGE], segs[si2], kc2, tid);
            CP_COMMIT();
        }
    }
    {
        const int pw = (total - 1) % NSTAGE;
        MBAR_WAIT(ctrl + 8 + pw * 8, mcnt[pw] & 1);
        mcnt[pw]++;
    }
    TC_FENCE_AFTER();
}
#endif // HAS_TC

// ---------------- grid barrier ----------------
__device__ unsigned g_count;
__device__ volatile unsigned g_gen;
__device__ __forceinline__ void gsync() {
    __threadfence();
    __syncthreads();
    if (threadIdx.x == 0) {
        unsigned gen = g_gen;
        if (atomicAdd(&g_count, 1u) == (unsigned)NB - 1u) {
            g_count = 0;
            __threadfence();
            g_gen = gen + 1u;
        } else {
            while (g_gen == gen) __nanosleep(64);
            __threadfence();
        }
    }
    __syncthreads();
}

// ---------------- fp32 fallback GEMM ----------------
struct SmemTiles {
    float As[8][132];
    float Bs[8][132];
};
__device__ __noinline__ void gemm_tile(
    SmemTiles* smB,
    float* __restrict__ C, int ldc,
    const float* __restrict__ A1, int lda1,
    const float* __restrict__ B1, int ldb1, int K1,
    const float* __restrict__ A2, int lda2,
    const float* __restrict__ B2, int ldb2, int K2,
    const float* __restrict__ bias, int m0, int n0, int act)
{
    const int tid = threadIdx.x;
    const int tx = tid & 15, ty = tid >> 4;
    const int arow = tid >> 1, acol = (tid & 1) * 4;
    const int brow = tid >> 5, bcol = (tid & 31) * 4;
    float acc[8][8];
#pragma unroll
    for (int i = 0; i < 8; i++)
#pragma unroll
        for (int j = 0; j < 8; j++) acc[i][j] = 0.f;
    int buf = 0;
    const int npass = A2 ? 2 : 1;
    for (int pass = 0; pass < npass; ++pass) {
        const float* A = pass ? A2 : A1;
        const float* B = pass ? B2 : B1;
        const int lda = pass ? lda2 : lda1;
        const int ldb = pass ? ldb2 : ldb1;
        const int K   = pass ? K2  : K1;
        float4 av = __ldcg((const float4*)(A + (size_t)(m0 + arow) * lda + acol));
        float4 bv = __ldcg((const float4*)(B + (size_t)(brow) * ldb + n0 + bcol));
        for (int k0 = 0; k0 < K; k0 += 8) {
            SmemTiles* sm = &smB[buf];
            sm->As[acol + 0][arow] = av.x;
            sm->As[acol + 1][arow] = av.y;
            sm->As[acol + 2][arow] = av.z;
            sm->As[acol + 3][arow] = av.w;
            *(float4*)&sm->Bs[brow][bcol] = bv;
            __syncthreads();
            if (k0 + 8 < K) {
                av = __ldcg((const float4*)(A + (size_t)(m0 + arow) * lda + k0 + 8 + acol));
                bv = __ldcg((const float4*)(B + (size_t)(k0 + 8 + brow) * ldb + n0 + bcol));
            }
#pragma unroll
            for (int k = 0; k < 8; k++) {
                float4 a0 = *(const float4*)&sm->As[k][ty * 8];
                float4 a1 = *(const float4*)&sm->As[k][ty * 8 + 4];
                float4 b0 = *(const float4*)&sm->Bs[k][tx * 8];
                float4 b1 = *(const float4*)&sm->Bs[k][tx * 8 + 4];
                float ar[8] = {a0.x, a0.y, a0.z, a0.w, a1.x, a1.y, a1.z, a1.w};
                float br[8] = {b0.x, b0.y, b0.z, b0.w, b1.x, b1.y, b1.z, b1.w};
#pragma unroll
                for (int i = 0; i < 8; i++)
#pragma unroll
                    for (int j = 0; j < 8; j++)
                        acc[i][j] = fmaf(ar[i], br[j], acc[i][j]);
            }
            buf ^= 1;
        }
    }
    float bv8[8];
#pragma unroll
    for (int j = 0; j < 8; j++) bv8[j] = bias ? bias[n0 + tx * 8 + j] : 0.f;
#pragma unroll
    for (int i = 0; i < 8; i++) {
        float r[8];
#pragma unroll
        for (int j = 0; j < 8; j++) {
            float v = acc[i][j] + bv8[j];
            if (act == 1)      v = tanhf(v);
            else if (act == 2) v = sigmoidf_(v);
            r[j] = v;
        }
        float* cp = C + (size_t)(m0 + ty * 8 + i) * ldc + n0 + tx * 8;
        *(float4*)(cp)     = make_float4(r[0], r[1], r[2], r[3]);
        *(float4*)(cp + 4) = make_float4(r[4], r[5], r[6], r[7]);
    }
}

// ---------------- persistent kernel ----------------
__global__ void __launch_bounds__(NT, 1) rgcn_persistent(
    const float* __restrict__ inputs, const float* __restrict__ A,
    const float* __restrict__ kernelW, const float* __restrict__ rkernel,
    const float* __restrict__ lstm_b,
    const float* __restrict__ W_gh, const float* __restrict__ b_gh,
    const float* __restrict__ W_gc, const float* __restrict__ b_gc,
    const float* __restrict__ W_hc, const float* __restrict__ W_hp,
    const float* __restrict__ b_h,
    const float* __restrict__ W_cc, const float* __restrict__ W_cp,
    const float* __restrict__ b_c,
    const float* __restrict__ W_out, const float* __restrict__ b_out,
    float* __restrict__ out)
{
    extern __shared__ char smraw[];
    const int bid = blockIdx.x;
    const int tid = threadIdx.x;
    const int wid = tid >> 5;
    const int lid = tid & 31;
    const size_t stateN = (size_t)N_NODES * H_DIM;
    const int gt = bid * NT + tid, gs = NB * NT;

    uint32_t sb_raw = smem_u32(smraw);
    uint32_t sb = (sb_raw + 1023u) & ~1023u;
    char* smb = smraw + (sb - sb_raw);
    SmemTiles* smB = (SmemTiles*)(smb + 1024);

#if HAS_TC
    uint32_t ctrl = sb;                     // [0] tmem ptr, [8],[16],[24] mbars
    uint32_t stage_u[NSTAGE] = {sb + 1024, sb + 1024 + STAGE_BYTES,
                                sb + 1024 + 2 * STAGE_BYTES};
    int mcnt[NSTAGE] = {0, 0, 0};
    if (tid == 0) { MBAR_INIT(ctrl + 8, 1); MBAR_INIT(ctrl + 16, 1); MBAR_INIT(ctrl + 24, 1); }
    if (wid == 0) TC_ALLOC(ctrl, 512);
    __syncthreads();
    uint32_t tmem_base;
    asm volatile("ld.shared.b32 %0, [%1];" : "=r"(tmem_base) : "r"(ctrl));

    // ---- one-time init ----
    for (int i = gt; i < (int)stateN; i += gs) {
        g_hhi[i] = __float2bfloat16(0.f); g_hlo[i] = __float2bfloat16(0.f);
        g_chi[i] = __float2bfloat16(0.f); g_clo[i] = __float2bfloat16(0.f);
    }
    for (size_t i = (size_t)gt; i < (size_t)N_NODES * N_NODES; i += (size_t)gs)
        bsplit(A[i], &g_Ahi[i], &g_Alo[i]);
    for (size_t i = (size_t)gt; i < (size_t)N_NODES * T_STEPS * D_IN; i += (size_t)gs)
        bsplit(inputs[i], &g_xhi[i], &g_xlo[i]);
    for (int i = gt; i < 4 * H_DIM * H_DIM; i += gs) {
        int n = i >> 8, k = i & 255;
        bsplit(rkernel[k * (4 * H_DIM) + n], &g_rkThi[i], &g_rkTlo[i]);
    }
    for (int i = gt; i < 4 * H_DIM * D_IN; i += gs) {
        int n = i >> 4, k = i & 15;
        bsplit(kernelW[k * (4 * H_DIM) + n], &g_kThi[i], &g_kTlo[i]);
    }
    for (int i = gt; i < H_DIM * H_DIM; i += gs) {
        int n = i >> 8, k = i & 255;
        bsplit(W_gh[k * H_DIM + n], &g_WghThi[i], &g_WghTlo[i]);
        bsplit(W_gc[k * H_DIM + n], &g_WgcThi[i], &g_WgcTlo[i]);
        bsplit(W_hc[k * H_DIM + n], &g_WhcThi[i], &g_WhcTlo[i]);
        bsplit(W_hp[k * H_DIM + n], &g_WhpThi[i], &g_WhpTlo[i]);
        bsplit(W_cc[k * H_DIM + n], &g_WccThi[i], &g_WccTlo[i]);
        bsplit(W_cp[k * H_DIM + n], &g_WcpThi[i], &g_WcpTlo[i]);
    }
#else
    for (int i = gt; i < (int)stateN; i += gs) { g_h[i] = 0.f; g_c[i] = 0.f; }
#endif
    gsync();

    const int m0 = (bid >> 2) * 128;
    const int n0 = (bid & 3) * 128;

    for (int t = 0; t < T_STEPS; ++t) {
        const int cur = t & 1, nxt = (t + 1) & 1;

#if HAS_TC
        const bf16* hphi = g_hhi + (size_t)cur * stateN;
        const bf16* hplo = g_hlo + (size_t)cur * stateN;
        const bf16* cphi = g_chi + (size_t)cur * stateN;
        const bf16* cplo = g_clo + (size_t)cur * stateN;

        if (t > 0) {
            int warp = bid * (NT / 32) + wid;
            for (int r = warp; r < N_NODES; r += NB * (NT / 32)) {
                float s0 = 0.f, s1 = 0.f;
#pragma unroll
                for (int j = 0; j < 8; j++) {
                    int k = lid + 32 * j;
                    size_t ix = (size_t)r * H_DIM + k;
                    float hv = __bfloat162float(__ldcg(hphi + ix)) +
                               __bfloat162float(__ldcg(hplo + ix));
                    s0 = fmaf(hv, W_out[2 * k + 0], s0);
                    s1 = fmaf(hv, W_out[2 * k + 1], s1);
                }
#pragma unroll
                for (int o = 16; o > 0; o >>= 1) {
                    s0 += __shfl_down_sync(0xffffffffu, s0, o);
                    s1 += __shfl_down_sync(0xffffffffu, s1, o);
                }
                if (lid == 0) {
                    size_t base = (size_t)r * T_STEPS * P_OUT + (size_t)(t - 1) * P_OUT;
                    out[base + 0] = s0 + b_out[0];
                    out[base + 1] = s1 + b_out[1];
                }
            }
        }

        // ---- PHASE A: G tile -> G^T split ----
        {
            const bool isH = (n0 < 256);
            Seg sg[1];
            sg[0].Ahi = (isH ? hphi : cphi) + (size_t)m0 * H_DIM;
            sg[0].Alo = (isH ? hplo : cplo) + (size_t)m0 * H_DIM;
            sg[0].lda = H_DIM;
            sg[0].Bhi = (isH ? g_WghThi : g_WgcThi) + (size_t)(n0 & 255) * H_DIM;
            sg[0].Blo = (isH ? g_WghTlo : g_WgcTlo) + (size_t)(n0 & 255) * H_DIM;
            sg[0].ldb = H_DIM;
            sg[0].nchunk = 4; sg[0].ksec = 8; sg[0].use_alo = 1;
            tc_tile_run(ctrl, stage_u, tmem_base, sg, 1, mcnt, tid, wid);
            const float* gb = isH ? b_gh : b_gc;
            if (wid < 4) {
                int row = m0 + wid * 32 + lid;
                uint32_t rg[32];
#pragma unroll 1
                for (int cb = 0; cb < 128; cb += 32) {
                    TC_LD_X32(rg, tmem_base + cb);
                    TC_WAIT_LD();
#pragma unroll
                    for (int jj = 0; jj < 32; jj++) {
                        int gcol = n0 + cb + jj;
                        float v = __uint_as_float(rg[jj]) + gb[gcol & 255];
                        bf16 hi, lo; bsplit(v, &hi, &lo);
                        g_GhiT[(size_t)gcol * N_NODES + row] = hi;
                        g_GloT[(size_t)gcol * N_NODES + row] = lo;
                    }
                }
                TC_FENCE_BEFORE();
            }
            __syncthreads();
        }
        // z tiles (2 per CTA)
#pragma unroll 1
        for (int zi = 0; zi < 2; zi++) {
            int zt = bid + zi * 128;
            int mz = (zt >> 3) * 128, nz = (zt & 7) * 128;
            Seg sg[2];
            sg[0].Ahi = g_xhi + (size_t)mz * (T_STEPS * D_IN) + (size_t)t * D_IN;
            sg[0].Alo = g_xlo + (size_t)mz * (T_STEPS * D_IN) + (size_t)t * D_IN;
            sg[0].lda = T_STEPS * D_IN;
            sg[0].Bhi = g_kThi + (size_t)nz * D_IN;
            sg[0].Blo = g_kTlo + (size_t)nz * D_IN;
            sg[0].ldb = D_IN;
            sg[0].nchunk = 1; sg[0].ksec = 2; sg[0].use_alo = 1;
            sg[1].Ahi = hphi + (size_t)mz * H_DIM;
            sg[1].Alo = hplo + (size_t)mz * H_DIM;
            sg[1].lda = H_DIM;
            sg[1].Bhi = g_rkThi + (size_t)nz * H_DIM;
            sg[1].Blo = g_rkTlo + (size_t)nz * H_DIM;
            sg[1].ldb = H_DIM;
            sg[1].nchunk = 4; sg[1].ksec = 8; sg[1].use_alo = 1;
            tc_tile_run(ctrl, stage_u, tmem_base, sg, 2, mcnt, tid, wid);
            if (wid < 4) {
                int row = mz + wid * 32 + lid;
                uint32_t rg[32];
#pragma unroll 1
                for (int cb = 0; cb < 128; cb += 32) {
                    TC_LD_X32(rg, tmem_base + cb);
                    TC_WAIT_LD();
#pragma unroll
                    for (int jj = 0; jj < 32; jj++) {
                        int zc = nz + cb + jj;
                        g_z[(size_t)row * (4 * H_DIM) + zc] =
                            __uint_as_float(rg[jj]) + lstm_b[zc];
                    }
                }
                TC_FENCE_BEFORE();
            }
            __syncthreads();
        }
        gsync();

        // ---- PHASE B ----
        for (int idx = gt; idx < N_NODES * H_DIM; idx += gs) {
            int n = idx >> 8, hh = idx & 255;
            const float* zr = g_z + (size_t)n * (4 * H_DIM);
            float zi = __ldcg(zr + hh);
            float zf = __ldcg(zr + H_DIM + hh);
            float zg = __ldcg(zr + 2 * H_DIM + hh);
            float zo = __ldcg(zr + 3 * H_DIM + hh);
            float cp = __bfloat162float(__ldcg(cphi + idx)) +
                       __bfloat162float(__ldcg(cplo + idx));
            float c = sigmoidf_(zf) * cp + sigmoidf_(zi) * tanhf(zg);
            bsplit(c, &g_ccurhi[idx], &g_ccurlo[idx]);
            bsplit(sigmoidf_(zo) * tanhf(c), &g_hcurhi[idx], &g_hcurlo[idx]);
        }
        __syncthreads();
        {
            // big GEMM: 2-term split (A is positive row-normalized; dropping
            // Alo*Ghi adds ~1e-3 rel err on HG, heavily damped downstream)
            Seg sg[1];
            sg[0].Ahi = g_Ahi + (size_t)m0 * N_NODES;
            sg[0].Alo = g_Alo + (size_t)m0 * N_NODES;
            sg[0].lda = N_NODES;
            sg[0].Bhi = g_GhiT + (size_t)n0 * N_NODES;
            sg[0].Blo = g_GloT + (size_t)n0 * N_NODES;
            sg[0].ldb = N_NODES;
            sg[0].nchunk = 64; sg[0].ksec = 8; sg[0].use_alo = 0;
            tc_tile_run(ctrl, stage_u, tmem_base, sg, 1, mcnt, tid, wid);
            if (wid < 4) {
                int row = m0 + wid * 32 + lid;
                uint32_t rg[32];
#pragma unroll 1
                for (int cb = 0; cb < 128; cb += 32) {
                    TC_LD_X32(rg, tmem_base + cb);
                    TC_WAIT_LD();
#pragma unroll
                    for (int jj = 0; jj < 32; jj++) {
                        float v = tanhf(__uint_as_float(rg[jj]));
                        bf16 hi, lo; bsplit(v, &hi, &lo);
                        size_t ix = (size_t)row * (2 * H_DIM) + n0 + cb + jj;
                        g_HGhi[ix] = hi; g_HGlo[ix] = lo;
                    }
                }
                TC_FENCE_BEFORE();
            }
            __syncthreads();
        }
        gsync();

        // ---- PHASE C ----
        {
            const bool isH = (bid < 64);
            int ci = isH ? bid : bid - 64;
            int mc = (ci >> 1) * 128, nc = (ci & 1) * 128;
            Seg sg[2];
            sg[0].Ahi = (isH ? g_hcurhi : g_ccurhi) + (size_t)mc * H_DIM;
            sg[0].Alo = (isH ? g_hcurlo : g_ccurlo) + (size_t)mc * H_DIM;
            sg[0].lda = H_DIM;
            sg[0].Bhi = (isH ? g_WhcThi : g_WccThi) + (size_t)nc * H_DIM;
            sg[0].Blo = (isH ? g_WhcTlo : g_WccTlo) + (size_t)nc * H_DIM;
            sg[0].ldb = H_DIM;
            sg[0].nchunk = 4; sg[0].ksec = 8; sg[0].use_alo = 1;
            sg[1].Ahi = g_HGhi + (size_t)mc * (2 * H_DIM) + (isH ? 0 : H_DIM);
            sg[1].Alo = g_HGlo + (size_t)mc * (2 * H_DIM) + (isH ? 0 : H_DIM);
            sg[1].lda = 2 * H_DIM;
            sg[1].Bhi = (isH ? g_WhpThi : g_WcpThi) + (size_t)nc * H_DIM;
            sg[1].Blo = (isH ? g_WhpTlo : g_WcpTlo) + (size_t)nc * H_DIM;
            sg[1].ldb = H_DIM;
            sg[1].nchunk = 4; sg[1].ksec = 8; sg[1].use_alo = 1;
            tc_tile_run(ctrl, stage_u, tmem_base, sg, 2, mcnt, tid, wid);
            const float* cbias = isH ? b_h : b_c;
            bf16* Sh = (isH ? g_hhi : g_chi) + (size_t)nxt * stateN;
            bf16* Sl = (isH ? g_hlo : g_clo) + (size_t)nxt * stateN;
            if (wid < 4) {
                int row = mc + wid * 32 + lid;
                uint32_t rg[32];
#pragma unroll 1
                for (int cb = 0; cb < 128; cb += 32) {
                    TC_LD_X32(rg, tmem_base + cb);
                    TC_WAIT_LD();
#pragma unroll
                    for (int jj = 0; jj < 32; jj++) {
                        int sc = nc + cb + jj;
                        float v = sigmoidf_(__uint_as_float(rg[jj]) + cbias[sc]);
                        bf16 hi, lo; bsplit(v, &hi, &lo);
                        size_t ix = (size_t)row * H_DIM + sc;
                        Sh[ix] = hi; Sl[ix] = lo;
                    }
                }
                TC_FENCE_BEFORE();
            }
            __syncthreads();
        }
        gsync();

#else   // ------------------- fp32 fallback path -------------------
        float* h_prev = g_h + (size_t)cur * stateN;
        float* c_prev = g_c + (size_t)cur * stateN;
        float* h_next = g_h + (size_t)nxt * stateN;
        float* c_next = g_c + (size_t)nxt * stateN;
        if (t > 0) {
            int warp = bid * (NT / 32) + wid;
            for (int r = warp; r < N_NODES; r += NB * (NT / 32)) {
                const float* hr = h_prev + (size_t)r * H_DIM;
                float s0 = 0.f, s1 = 0.f;
#pragma unroll
                for (int j = 0; j < 8; j++) {
                    int k = lid + 32 * j;
                    float hv = __ldcg(hr + k);
                    s0 = fmaf(hv, W_out[2 * k + 0], s0);
                    s1 = fmaf(hv, W_out[2 * k + 1], s1);
                }
#pragma unroll
                for (int o = 16; o > 0; o >>= 1) {
                    s0 += __shfl_down_sync(0xffffffffu, s0, o);
                    s1 += __shfl_down_sync(0xffffffffu, s1, o);
                }
                if (lid == 0) {
                    size_t base = (size_t)r * T_STEPS * P_OUT + (size_t)(t - 1) * P_OUT;
                    out[base + 0] = s0 + b_out[0];
                    out[base + 1] = s1 + b_out[1];
                }
            }
        }
#pragma unroll 1
        for (int tile = bid; tile < 384; tile += NB) {
            if (tile < 64) {
                int tm = (tile >> 1) * 128, tn = (tile & 1) * 128;
                gemm_tile(smB, g_G, 2 * H_DIM, h_prev, H_DIM, W_gh, H_DIM, H_DIM,
                          nullptr, 0, nullptr, 0, 0, b_gh, tm, tn, 0);
            } else if (tile < 128) {
                int tt = tile - 64;
                int tm = (tt >> 1) * 128, tn = (tt & 1) * 128;
                gemm_tile(smB, g_G + H_DIM, 2 * H_DIM, c_prev, H_DIM, W_gc, H_DIM, H_DIM,
                          nullptr, 0, nullptr, 0, 0, b_gc, tm, tn, 0);
            } else {
                int tz = tile - 128;
                int tm = (tz >> 3) * 128, tn = (tz & 7) * 128;
                gemm_tile(smB, g_z, 4 * H_DIM,
                          inputs + (size_t)t * D_IN, T_STEPS * D_IN, kernelW, 4 * H_DIM, D_IN,
                          h_prev, H_DIM, rkernel, 4 * H_DIM, H_DIM,
                          lstm_b, tm, tn, 0);
            }
        }
        gsync();
        for (int idx = gt; idx < N_NODES * H_DIM; idx += gs) {
            int n = idx >> 8, hh = idx & 255;
            const float* zr = g_z + (size_t)n * (4 * H_DIM);
            float zi = __ldcg(zr + hh);
            float zf = __ldcg(zr + H_DIM + hh);
            float zg = __ldcg(zr + 2 * H_DIM + hh);
            float zo = __ldcg(zr + 3 * H_DIM + hh);
            float c = sigmoidf_(zf) * __ldcg(c_prev + idx) + sigmoidf_(zi) * tanhf(zg);
            g_ccur[idx] = c;
            g_hcur[idx] = sigmoidf_(zo) * tanhf(c);
        }
        __syncthreads();
        gemm_tile(smB, g_HG, 2 * H_DIM, A, N_NODES, g_G, 2 * H_DIM, N_NODES,
                  nullptr, 0, nullptr, 0, 0, nullptr, m0, n0, 1);
        gsync();
        if (bid < 64) {
            int tm = (bid >> 1) * 128, tn = (bid & 1) * 128;
            gemm_tile(smB, h_next, H_DIM,
                      g_hcur, H_DIM, W_hc, H_DIM, H_DIM,
                      g_HG, 2 * H_DIM, W_hp, H_DIM, H_DIM,
                      b_h, tm, tn, 2);
        } else {
            int tt = bid - 64;
            int tm = (tt >> 1) * 128, tn = (tt & 1) * 128;
            gemm_tile(smB, c_next, H_DIM,
                      g_ccur, H_DIM, W_cc, H_DIM, H_DIM,
                      g_HG + H_DIM, 2 * H_DIM, W_cp, H_DIM, H_DIM,
                      b_c, tm, tn, 2);
        }
        gsync();
#endif
    }

    // final output row for t = T-1
    {
        int warp = bid * (NT / 32) + wid;
        const int fb = T_STEPS & 1;
        for (int r = warp; r < N_NODES; r += NB * (NT / 32)) {
            float s0 = 0.f, s1 = 0.f;
#pragma unroll
            for (int j = 0; j < 8; j++) {
                int k = lid + 32 * j;
#if HAS_TC
                size_t ix = (size_t)fb * stateN + (size_t)r * H_DIM + k;
                float hv = __bfloat162float(__ldcg(g_hhi + ix)) +
                           __bfloat162float(__ldcg(g_hlo + ix));
#else
                float hv = __ldcg(g_h + (size_t)fb * stateN + (size_t)r * H_DIM + k);
#endif
                s0 = fmaf(hv, W_out[2 * k + 0], s0);
                s1 = fmaf(hv, W_out[2 * k + 1], s1);
            }
#pragma unroll
            for (int o = 16; o > 0; o >>= 1) {
                s0 += __shfl_down_sync(0xffffffffu, s0, o);
                s1 += __shfl_down_sync(0xffffffffu, s1, o);
            }
            if (lid == 0) {
                size_t base = (size_t)r * T_STEPS * P_OUT + (size_t)(T_STEPS - 1) * P_OUT;
                out[base + 0] = s0 + b_out[0];
                out[base + 1] = s1 + b_out[1];
            }
        }
    }

#if HAS_TC
    __syncthreads();
    if (wid == 0) TC_DEALLOC(tmem_base, 512);
#endif
}

// ---------------- launch ----------------
extern "C" void kernel_launch(void* const* d_in, const int* in_sizes, int n_in,
                              void* d_out, int out_size)
{
    const float* inputs  = (const float*)d_in[0];
    const float* A       = (const float*)d_in[1];
    const float* kernelW = (const float*)d_in[2];
    const float* rkernel = (const float*)d_in[3];
    const float* lstm_b  = (const float*)d_in[4];
    const float* W_gh    = (const float*)d_in[5];
    const float* b_gh    = (const float*)d_in[6];
    const float* W_gc    = (const float*)d_in[7];
    const float* b_gc    = (const float*)d_in[8];
    const float* W_hc    = (const float*)d_in[9];
    const float* W_hp    = (const float*)d_in[10];
    const float* b_h     = (const float*)d_in[11];
    const float* W_cc    = (const float*)d_in[12];
    const float* W_cp    = (const float*)d_in[13];
    const float* b_c     = (const float*)d_in[14];
    const float* W_out   = (const float*)d_in[15];
    const float* b_out   = (const float*)d_in[16];
    float* out = (float*)d_out;

    cudaFuncSetAttribute(rgcn_persistent,
                         cudaFuncAttributeMaxDynamicSharedMemorySize, SMEM_DYN);
    rgcn_persistent<<<NB, NT, SMEM_DYN>>>(inputs, A, kernelW, rkernel, lstm_b,
                                          W_gh, b_gh, W_gc, b_gc,
                                          W_hc, W_hp, b_h, W_cc, W_cp, b_c,
                                          W_out, b_out, out);
}

// round 15
// speedup vs baseline: 2.1274x; 1.2686x over previous
#include <cuda_runtime.h>
#include <cuda_bf16.h>
#include <math.h>
#include <stdint.h>

#define N_NODES 4096
#define T_STEPS 365
#define D_IN    16
#define H_DIM   256
#define P_OUT   2
#define NB      128
#define NT      256

#if defined(__CUDA_ARCH__) && (defined(__CUDA_ARCH_FEAT_SM103_ALL) || defined(__CUDA_ARCH_FEAT_SM100_ALL))
#define HAS_TC 1
#else
#define HAS_TC 0
#endif

#define KC 64
#define NSTAGE 3
#define STAGE_BYTES 65536          // generic: AHI|ALO|BHI|BLO 16K each
#define OFF_AHI 0                  // big:    A-K0|A-K1|B-K0|B-K1 16K each
#define OFF_ALO 16384
#define OFF_BHI 32768
#define OFF_BLO 49152
#define SMEM_DYN (1024 + 1024 + NSTAGE * STAGE_BYTES)

typedef __nv_bfloat16 bf16;

// ---------------- device scratch (TC path) ----------------
__device__ __align__(128) bf16 g_hhi[2 * N_NODES * H_DIM];
__device__ __align__(128) bf16 g_hlo[2 * N_NODES * H_DIM];
__device__ __align__(128) bf16 g_chi[2 * N_NODES * H_DIM];
__device__ __align__(128) bf16 g_clo[2 * N_NODES * H_DIM];
__device__ __align__(128) bf16 g_HGhi[N_NODES * 2 * H_DIM];
__device__ __align__(128) bf16 g_HGlo[N_NODES * 2 * H_DIM];
__device__ __align__(128) bf16 g_hcurhi[N_NODES * H_DIM];
__device__ __align__(128) bf16 g_hcurlo[N_NODES * H_DIM];
__device__ __align__(128) bf16 g_ccurhi[N_NODES * H_DIM];
__device__ __align__(128) bf16 g_ccurlo[N_NODES * H_DIM];
__device__ __align__(128) bf16 g_GhiT[2 * H_DIM * N_NODES];
__device__ __align__(128) bf16 g_GloT[2 * H_DIM * N_NODES];
__device__ __align__(128) bf16 g_Ahi[(size_t)N_NODES * N_NODES];
__device__ __align__(128) bf16 g_Alo[(size_t)N_NODES * N_NODES];
__device__ __align__(128) bf16 g_xhi[(size_t)N_NODES * T_STEPS * D_IN];
__device__ __align__(128) bf16 g_xlo[(size_t)N_NODES * T_STEPS * D_IN];
__device__ __align__(128) bf16 g_rkThi[4 * H_DIM * H_DIM], g_rkTlo[4 * H_DIM * H_DIM];
__device__ __align__(128) bf16 g_kThi [4 * H_DIM * D_IN],  g_kTlo [4 * H_DIM * D_IN];
__device__ __align__(128) bf16 g_WghThi[H_DIM * H_DIM], g_WghTlo[H_DIM * H_DIM];
__device__ __align__(128) bf16 g_WgcThi[H_DIM * H_DIM], g_WgcTlo[H_DIM * H_DIM];
__device__ __align__(128) bf16 g_WhcThi[H_DIM * H_DIM], g_WhcTlo[H_DIM * H_DIM];
__device__ __align__(128) bf16 g_WhpThi[H_DIM * H_DIM], g_WhpTlo[H_DIM * H_DIM];
__device__ __align__(128) bf16 g_WccThi[H_DIM * H_DIM], g_WccTlo[H_DIM * H_DIM];
__device__ __align__(128) bf16 g_WcpThi[H_DIM * H_DIM], g_WcpTlo[H_DIM * H_DIM];
__device__ float g_z[N_NODES * 4 * H_DIM];
// fallback (fp32) scratch
__device__ float g_h[2 * N_NODES * H_DIM];
__device__ float g_c[2 * N_NODES * H_DIM];
__device__ float g_G [N_NODES * 2 * H_DIM];
__device__ float g_HG[N_NODES * 2 * H_DIM];
__device__ float g_hcur[N_NODES * H_DIM];
__device__ float g_ccur[N_NODES * H_DIM];

// ---------------- helpers ----------------
__device__ __forceinline__ uint32_t smem_u32(const void* p) {
    uint32_t a;
    asm("{ .reg .u64 t; cvta.to.shared.u64 t, %1; cvt.u32.u64 %0, t; }" : "=r"(a) : "l"(p));
    return a;
}
#define SW128(o) ((o) ^ (((o) >> 3) & 0x70))
__device__ __forceinline__ float sigmoidf_(float x) { return 1.f / (1.f + expf(-x)); }
__device__ __forceinline__ void bsplit(float v, bf16* hi, bf16* lo) {
    bf16 h = __float2bfloat16(v);
    *hi = h;
    *lo = __float2bfloat16(v - __bfloat162float(h));
}

#if HAS_TC
__device__ __forceinline__ uint32_t elect_one() {
    uint32_t p;
    asm volatile("{ .reg .pred p; elect.sync _|p, 0xFFFFFFFF; selp.b32 %0, 1, 0, p; }" : "=r"(p));
    return p;
}
#define CP_ASYNC16(dst, src) \
    asm volatile("cp.async.cg.shared.global [%0], [%1], 16;" :: "r"(dst), "l"(src) : "memory")
#define CP_COMMIT()  asm volatile("cp.async.commit_group;" ::: "memory")
#define CP_WAIT0()   asm volatile("cp.async.wait_group 0;" ::: "memory")
#define CP_WAIT1()   asm volatile("cp.async.wait_group 1;" ::: "memory")
#define MBAR_INIT(a, c) \
    asm volatile("mbarrier.init.shared.b64 [%0], %1;" :: "r"(a), "r"(c) : "memory")
#define MBAR_WAIT(a, par) do { \
    uint32_t _m = (a), _p = (par), _d; \
    asm volatile("{ .reg .pred p; mbarrier.try_wait.parity.acquire.cta.shared::cta.b64 p, [%1], %2; selp.b32 %0,1,0,p; }" \
        : "=r"(_d) : "r"(_m), "r"(_p) : "memory"); \
    if (!_d) { \
        asm volatile("{ .reg .pred P1; WL_%=: mbarrier.try_wait.parity.acquire.cta.shared::cta.b64 P1, [%0], %1, 0x989680; @P1 bra.uni WD_%=; bra.uni WL_%=; WD_%=: }" \
            :: "r"(_m), "r"(_p) : "memory"); \
    } } while (0)
#define TC_ALLOC(sp, n)   asm volatile("tcgen05.alloc.cta_group::1.sync.aligned.shared::cta.b32 [%0], %1;" :: "r"(sp), "r"(n) : "memory")
#define TC_DEALLOC(t, n)  asm volatile("tcgen05.dealloc.cta_group::1.sync.aligned.b32 %0, %1;" :: "r"(t), "r"(n))
#define TC_COMMIT(mb)     asm volatile("tcgen05.commit.cta_group::1.mbarrier::arrive::one.shared::cluster.b64 [%0];" :: "r"(mb) : "memory")
#define TC_FENCE_AFTER()  asm volatile("tcgen05.fence::after_thread_sync;" ::: "memory")
#define TC_FENCE_BEFORE() asm volatile("tcgen05.fence::before_thread_sync;" ::: "memory")
#define TC_WAIT_LD()      asm volatile("tcgen05.wait::ld.sync.aligned;" ::: "memory")
#define FENCE_ASYNC()     asm volatile("fence.proxy.async.shared::cta;" ::: "memory")

static __device__ __forceinline__ uint64_t make_desc_k(uint32_t addr) {
    return ((uint64_t)2 << 61) | ((uint64_t)1 << 46) | ((uint64_t)64 << 32) |
           ((uint64_t)1 << 16) | ((uint64_t)(addr >> 4) & 0x3FFF);
}
// kind::f16, d=f32, a=bf16, b=bf16, K-major, N=128, M=128
#define MMA_IDESC ((1u<<4)|(1u<<7)|(1u<<10)|(16u<<17)|(8u<<24))
__device__ __forceinline__ void mma_ss(uint32_t d, uint64_t ad, uint64_t bd, bool acc) {
    uint32_t en = acc ? 1u : 0u;
    asm volatile(
        "{ .reg .pred p; setp.ne.u32 p, %5, 0;\n\t"
        "tcgen05.mma.cta_group::1.kind::f16 [%0], %1, %2, %3, {%4,%4,%4,%4}, p; }"
        :: "r"(d), "l"(ad), "l"(bd), "r"(MMA_IDESC), "r"(0u), "r"(en) : "memory");
}
#define TC_LD_X32(r, ta) \
    asm volatile("tcgen05.ld.sync.aligned.32x32b.x32.b32 " \
        "{%0,%1,%2,%3,%4,%5,%6,%7,%8,%9,%10,%11,%12,%13,%14,%15," \
        "%16,%17,%18,%19,%20,%21,%22,%23,%24,%25,%26,%27,%28,%29,%30,%31}, [%32];" \
        : "=r"((r)[0]),"=r"((r)[1]),"=r"((r)[2]),"=r"((r)[3]),"=r"((r)[4]),"=r"((r)[5]),"=r"((r)[6]),"=r"((r)[7]), \
          "=r"((r)[8]),"=r"((r)[9]),"=r"((r)[10]),"=r"((r)[11]),"=r"((r)[12]),"=r"((r)[13]),"=r"((r)[14]),"=r"((r)[15]), \
          "=r"((r)[16]),"=r"((r)[17]),"=r"((r)[18]),"=r"((r)[19]),"=r"((r)[20]),"=r"((r)[21]),"=r"((r)[22]),"=r"((r)[23]), \
          "=r"((r)[24]),"=r"((r)[25]),"=r"((r)[26]),"=r"((r)[27]),"=r"((r)[28]),"=r"((r)[29]),"=r"((r)[30]),"=r"((r)[31]) \
        : "r"(ta))

struct Seg {
    const bf16* Ahi; const bf16* Alo; int lda;
    const bf16* Bhi; const bf16* Blo; int ldb;
    int nchunk;
    int ksec;          // valid 16B sections per chunk row (8 or 2)
    int use_alo;
};

__device__ __forceinline__ void seg_of(const Seg* segs, int c, int& si, int& kc) {
    if (c < segs[0].nchunk) { si = 0; kc = c * KC; }
    else                    { si = 1; kc = (c - segs[0].nchunk) * KC; }
}

__device__ __forceinline__ void load_chunk(uint32_t st, const Seg& sg, int kc, int tid) {
    const int ksec = sg.ksec;
    const int ua = sg.use_alo;
#pragma unroll 4
    for (int q = tid; q < 1024; q += NT) {
        int row = q >> 3, sc = q & 7;
        if (sc < ksec) {
            uint32_t d = SW128((uint32_t)(row * 128 + sc * 16));
            CP_ASYNC16(st + OFF_AHI + d, sg.Ahi + (size_t)row * sg.lda + kc + sc * 8);
            if (ua)
                CP_ASYNC16(st + OFF_ALO + d, sg.Alo + (size_t)row * sg.lda + kc + sc * 8);
            CP_ASYNC16(st + OFF_BHI + d, sg.Bhi + (size_t)row * sg.ldb + kc + sc * 8);
            CP_ASYNC16(st + OFF_BLO + d, sg.Blo + (size_t)row * sg.ldb + kc + sc * 8);
        }
    }
}

// ---- generic 3-stage pipelined tile (R14-proven skeleton) ----
__device__ __noinline__ void tc_tile_run(uint32_t ctrl, const uint32_t* stage_u,
                                         uint32_t tmem, const Seg* segs, int nseg,
                                         int* mcnt, int tid, int wid)
{
    int total = segs[0].nchunk;
    if (nseg > 1) total += segs[1].nchunk;

    {
        int si, kc;
        seg_of(segs, 0, si, kc);
        load_chunk(stage_u[0], segs[si], kc, tid);
        CP_COMMIT();
        if (total > 1) {
            seg_of(segs, 1, si, kc);
            load_chunk(stage_u[1], segs[si], kc, tid);
            CP_COMMIT();
        }
    }

    for (int cc = 0; cc < total; ++cc) {
        const int s = cc % NSTAGE;
        int si, kc;
        seg_of(segs, cc, si, kc);
        const int nks = segs[si].ksec >> 1;
        if (cc + 1 < total) CP_WAIT1(); else CP_WAIT0();
        __syncthreads();
        if (wid == 0) {
            FENCE_ASYNC();
            if (elect_one()) {
                uint64_t aHi = make_desc_k(stage_u[s] + OFF_AHI);
                uint64_t bHi = make_desc_k(stage_u[s] + OFF_BHI);
                uint64_t bLo = make_desc_k(stage_u[s] + OFF_BLO);
                for (int ks = 0; ks < nks; ks++)
                    mma_ss(tmem, aHi + ks * 2, bHi + ks * 2, !(cc == 0 && ks == 0));
                for (int ks = 0; ks < nks; ks++)
                    mma_ss(tmem, aHi + ks * 2, bLo + ks * 2, true);
                if (segs[si].use_alo) {
                    uint64_t aLo = make_desc_k(stage_u[s] + OFF_ALO);
                    for (int ks = 0; ks < nks; ks++)
                        mma_ss(tmem, aLo + ks * 2, bHi + ks * 2, true);
                }
                TC_COMMIT(ctrl + 8 + s * 8);
            }
        }
        if (cc >= 1) {
            const int pw = (cc - 1) % NSTAGE;
            MBAR_WAIT(ctrl + 8 + pw * 8, mcnt[pw] & 1);
            mcnt[pw]++;
        }
        if (cc + 2 < total) {
            int si2, kc2;
            seg_of(segs, cc + 2, si2, kc2);
            load_chunk(stage_u[(cc + 2) % NSTAGE], segs[si2], kc2, tid);
            CP_COMMIT();
        }
    }
    {
        const int pw = (total - 1) % NSTAGE;
        MBAR_WAIT(ctrl + 8 + pw * 8, mcnt[pw] & 1);
        mcnt[pw]++;
    }
    TC_FENCE_AFTER();
}

// ---- specialized big-GEMM runner: 1-term (Ahi@Bhi), K-chunks of 128 ----
// Stage layout: [0,16K) A K-block0, [16K,32K) A K-block1,
//               [32K,48K) B K-block0, [48K,64K) B K-block1. Each block is a
// standard 128-row x 64-col SW128 K-major tile; desc per block, +ks*2 stepping.
__device__ __forceinline__ void load_big(uint32_t st, const bf16* Ab, const bf16* Bb,
                                         int kc, int tid) {
#pragma unroll 8
    for (int q = tid; q < 2048; q += NT) {
        int row = q >> 4, sec = q & 15;
        int kb = sec >> 3, sc = sec & 7;
        uint32_t d = SW128((uint32_t)(row * 128 + sc * 16)) + kb * 16384;
        size_t so = (size_t)row * N_NODES + kc + kb * 64 + sc * 8;
        CP_ASYNC16(st + d,         Ab + so);
        CP_ASYNC16(st + 32768 + d, Bb + so);
    }
}

__device__ __noinline__ void tc_big_run(uint32_t ctrl, const uint32_t* stage_u,
                                        uint32_t tmem, const bf16* Ab, const bf16* Bb,
                                        int* mcnt, int tid, int wid)
{
    const int total = N_NODES / 128;   // 32 chunks of K=128
    load_big(stage_u[0], Ab, Bb, 0, tid);
    CP_COMMIT();
    load_big(stage_u[1], Ab, Bb, 128, tid);
    CP_COMMIT();

    for (int cc = 0; cc < total; ++cc) {
        const int s = cc % NSTAGE;
        if (cc + 1 < total) CP_WAIT1(); else CP_WAIT0();
        __syncthreads();
        if (wid == 0) {
            FENCE_ASYNC();
            if (elect_one()) {
#pragma unroll
                for (int kb = 0; kb < 2; kb++) {
                    uint64_t aD = make_desc_k(stage_u[s] + kb * 16384);
                    uint64_t bD = make_desc_k(stage_u[s] + 32768 + kb * 16384);
#pragma unroll
                    for (int ks = 0; ks < 4; ks++)
                        mma_ss(tmem, aD + ks * 2, bD + ks * 2,
                               !(cc == 0 && kb == 0 && ks == 0));
                }
                TC_COMMIT(ctrl + 8 + s * 8);
            }
        }
        if (cc >= 1) {
            const int pw = (cc - 1) % NSTAGE;
            MBAR_WAIT(ctrl + 8 + pw * 8, mcnt[pw] & 1);
            mcnt[pw]++;
        }
        if (cc + 2 < total) {
            load_big(stage_u[(cc + 2) % NSTAGE], Ab, Bb, (cc + 2) * 128, tid);
            CP_COMMIT();
        }
    }
    {
        const int pw = (total - 1) % NSTAGE;
        MBAR_WAIT(ctrl + 8 + pw * 8, mcnt[pw] & 1);
        mcnt[pw]++;
    }
    TC_FENCE_AFTER();
}
#endif // HAS_TC

// ---------------- grid barrier ----------------
__device__ unsigned g_count;
__device__ volatile unsigned g_gen;
__device__ __forceinline__ void gsync() {
    __threadfence();
    __syncthreads();
    if (threadIdx.x == 0) {
        unsigned gen = g_gen;
        if (atomicAdd(&g_count, 1u) == (unsigned)NB - 1u) {
            g_count = 0;
            __threadfence();
            g_gen = gen + 1u;
        } else {
            while (g_gen == gen) __nanosleep(64);
            __threadfence();
        }
    }
    __syncthreads();
}

// ---------------- fp32 fallback GEMM ----------------
struct SmemTiles {
    float As[8][132];
    float Bs[8][132];
};
__device__ __noinline__ void gemm_tile(
    SmemTiles* smB,
    float* __restrict__ C, int ldc,
    const float* __restrict__ A1, int lda1,
    const float* __restrict__ B1, int ldb1, int K1,
    const float* __restrict__ A2, int lda2,
    const float* __restrict__ B2, int ldb2, int K2,
    const float* __restrict__ bias, int m0, int n0, int act)
{
    const int tid = threadIdx.x;
    const int tx = tid & 15, ty = tid >> 4;
    const int arow = tid >> 1, acol = (tid & 1) * 4;
    const int brow = tid >> 5, bcol = (tid & 31) * 4;
    float acc[8][8];
#pragma unroll
    for (int i = 0; i < 8; i++)
#pragma unroll
        for (int j = 0; j < 8; j++) acc[i][j] = 0.f;
    int buf = 0;
    const int npass = A2 ? 2 : 1;
    for (int pass = 0; pass < npass; ++pass) {
        const float* A = pass ? A2 : A1;
        const float* B = pass ? B2 : B1;
        const int lda = pass ? lda2 : lda1;
        const int ldb = pass ? ldb2 : ldb1;
        const int K   = pass ? K2  : K1;
        float4 av = __ldcg((const float4*)(A + (size_t)(m0 + arow) * lda + acol));
        float4 bv = __ldcg((const float4*)(B + (size_t)(brow) * ldb + n0 + bcol));
        for (int k0 = 0; k0 < K; k0 += 8) {
            SmemTiles* sm = &smB[buf];
            sm->As[acol + 0][arow] = av.x;
            sm->As[acol + 1][arow] = av.y;
            sm->As[acol + 2][arow] = av.z;
            sm->As[acol + 3][arow] = av.w;
            *(float4*)&sm->Bs[brow][bcol] = bv;
            __syncthreads();
            if (k0 + 8 < K) {
                av = __ldcg((const float4*)(A + (size_t)(m0 + arow) * lda + k0 + 8 + acol));
                bv = __ldcg((const float4*)(B + (size_t)(k0 + 8 + brow) * ldb + n0 + bcol));
            }
#pragma unroll
            for (int k = 0; k < 8; k++) {
                float4 a0 = *(const float4*)&sm->As[k][ty * 8];
                float4 a1 = *(const float4*)&sm->As[k][ty * 8 + 4];
                float4 b0 = *(const float4*)&sm->Bs[k][tx * 8];
                float4 b1 = *(const float4*)&sm->Bs[k][tx * 8 + 4];
                float ar[8] = {a0.x, a0.y, a0.z, a0.w, a1.x, a1.y, a1.z, a1.w};
                float br[8] = {b0.x, b0.y, b0.z, b0.w, b1.x, b1.y, b1.z, b1.w};
#pragma unroll
                for (int i = 0; i < 8; i++)
#pragma unroll
                    for (int j = 0; j < 8; j++)
                        acc[i][j] = fmaf(ar[i], br[j], acc[i][j]);
            }
            buf ^= 1;
        }
    }
    float bv8[8];
#pragma unroll
    for (int j = 0; j < 8; j++) bv8[j] = bias ? bias[n0 + tx * 8 + j] : 0.f;
#pragma unroll
    for (int i = 0; i < 8; i++) {
        float r[8];
#pragma unroll
        for (int j = 0; j < 8; j++) {
            float v = acc[i][j] + bv8[j];
            if (act == 1)      v = tanhf(v);
            else if (act == 2) v = sigmoidf_(v);
            r[j] = v;
        }
        float* cp = C + (size_t)(m0 + ty * 8 + i) * ldc + n0 + tx * 8;
        *(float4*)(cp)     = make_float4(r[0], r[1], r[2], r[3]);
        *(float4*)(cp + 4) = make_float4(r[4], r[5], r[6], r[7]);
    }
}

// ---------------- persistent kernel ----------------
__global__ void __launch_bounds__(NT, 1) rgcn_persistent(
    const float* __restrict__ inputs, const float* __restrict__ A,
    const float* __restrict__ kernelW, const float* __restrict__ rkernel,
    const float* __restrict__ lstm_b,
    const float* __restrict__ W_gh, const float* __restrict__ b_gh,
    const float* __restrict__ W_gc, const float* __restrict__ b_gc,
    const float* __restrict__ W_hc, const float* __restrict__ W_hp,
    const float* __restrict__ b_h,
    const float* __restrict__ W_cc, const float* __restrict__ W_cp,
    const float* __restrict__ b_c,
    const float* __restrict__ W_out, const float* __restrict__ b_out,
    float* __restrict__ out)
{
    extern __shared__ char smraw[];
    const int bid = blockIdx.x;
    const int tid = threadIdx.x;
    const int wid = tid >> 5;
    const int lid = tid & 31;
    const size_t stateN = (size_t)N_NODES * H_DIM;
    const int gt = bid * NT + tid, gs = NB * NT;

    uint32_t sb_raw = smem_u32(smraw);
    uint32_t sb = (sb_raw + 1023u) & ~1023u;
    char* smb = smraw + (sb - sb_raw);
    SmemTiles* smB = (SmemTiles*)(smb + 1024);

#if HAS_TC
    uint32_t ctrl = sb;
    uint32_t stage_u[NSTAGE] = {sb + 1024, sb + 1024 + STAGE_BYTES,
                                sb + 1024 + 2 * STAGE_BYTES};
    int mcnt[NSTAGE] = {0, 0, 0};
    if (tid == 0) { MBAR_INIT(ctrl + 8, 1); MBAR_INIT(ctrl + 16, 1); MBAR_INIT(ctrl + 24, 1); }
    if (wid == 0) TC_ALLOC(ctrl, 512);
    __syncthreads();
    uint32_t tmem_base;
    asm volatile("ld.shared.b32 %0, [%1];" : "=r"(tmem_base) : "r"(ctrl));

    // ---- one-time init ----
    for (int i = gt; i < (int)stateN; i += gs) {
        g_hhi[i] = __float2bfloat16(0.f); g_hlo[i] = __float2bfloat16(0.f);
        g_chi[i] = __float2bfloat16(0.f); g_clo[i] = __float2bfloat16(0.f);
    }
    for (size_t i = (size_t)gt; i < (size_t)N_NODES * N_NODES; i += (size_t)gs)
        bsplit(A[i], &g_Ahi[i], &g_Alo[i]);
    for (size_t i = (size_t)gt; i < (size_t)N_NODES * T_STEPS * D_IN; i += (size_t)gs)
        bsplit(inputs[i], &g_xhi[i], &g_xlo[i]);
    for (int i = gt; i < 4 * H_DIM * H_DIM; i += gs) {
        int n = i >> 8, k = i & 255;
        bsplit(rkernel[k * (4 * H_DIM) + n], &g_rkThi[i], &g_rkTlo[i]);
    }
    for (int i = gt; i < 4 * H_DIM * D_IN; i += gs) {
        int n = i >> 4, k = i & 15;
        bsplit(kernelW[k * (4 * H_DIM) + n], &g_kThi[i], &g_kTlo[i]);
    }
    for (int i = gt; i < H_DIM * H_DIM; i += gs) {
        int n = i >> 8, k = i & 255;
        bsplit(W_gh[k * H_DIM + n], &g_WghThi[i], &g_WghTlo[i]);
        bsplit(W_gc[k * H_DIM + n], &g_WgcThi[i], &g_WgcTlo[i]);
        bsplit(W_hc[k * H_DIM + n], &g_WhcThi[i], &g_WhcTlo[i]);
        bsplit(W_hp[k * H_DIM + n], &g_WhpThi[i], &g_WhpTlo[i]);
        bsplit(W_cc[k * H_DIM + n], &g_WccThi[i], &g_WccTlo[i]);
        bsplit(W_cp[k * H_DIM + n], &g_WcpThi[i], &g_WcpTlo[i]);
    }
#else
    for (int i = gt; i < (int)stateN; i += gs) { g_h[i] = 0.f; g_c[i] = 0.f; }
#endif
    gsync();

    const int m0 = (bid >> 2) * 128;
    const int n0 = (bid & 3) * 128;

    for (int t = 0; t < T_STEPS; ++t) {
        const int cur = t & 1, nxt = (t + 1) & 1;

#if HAS_TC
        const bf16* hphi = g_hhi + (size_t)cur * stateN;
        const bf16* hplo = g_hlo + (size_t)cur * stateN;
        const bf16* cphi = g_chi + (size_t)cur * stateN;
        const bf16* cplo = g_clo + (size_t)cur * stateN;

        if (t > 0) {
            int warp = bid * (NT / 32) + wid;
            for (int r = warp; r < N_NODES; r += NB * (NT / 32)) {
                float s0 = 0.f, s1 = 0.f;
#pragma unroll
                for (int j = 0; j < 8; j++) {
                    int k = lid + 32 * j;
                    size_t ix = (size_t)r * H_DIM + k;
                    float hv = __bfloat162float(__ldcg(hphi + ix)) +
                               __bfloat162float(__ldcg(hplo + ix));
                    s0 = fmaf(hv, W_out[2 * k + 0], s0);
                    s1 = fmaf(hv, W_out[2 * k + 1], s1);
                }
#pragma unroll
                for (int o = 16; o > 0; o >>= 1) {
                    s0 += __shfl_down_sync(0xffffffffu, s0, o);
                    s1 += __shfl_down_sync(0xffffffffu, s1, o);
                }
                if (lid == 0) {
                    size_t base = (size_t)r * T_STEPS * P_OUT + (size_t)(t - 1) * P_OUT;
                    out[base + 0] = s0 + b_out[0];
                    out[base + 1] = s1 + b_out[1];
                }
            }
        }

        // ---- PHASE A: G tile -> G^T split ----
        {
            const bool isH = (n0 < 256);
            Seg sg[1];
            sg[0].Ahi = (isH ? hphi : cphi) + (size_t)m0 * H_DIM;
            sg[0].Alo = (isH ? hplo : cplo) + (size_t)m0 * H_DIM;
            sg[0].lda = H_DIM;
            sg[0].Bhi = (isH ? g_WghThi : g_WgcThi) + (size_t)(n0 & 255) * H_DIM;
            sg[0].Blo = (isH ? g_WghTlo : g_WgcTlo) + (size_t)(n0 & 255) * H_DIM;
            sg[0].ldb = H_DIM;
            sg[0].nchunk = 4; sg[0].ksec = 8; sg[0].use_alo = 1;
            tc_tile_run(ctrl, stage_u, tmem_base, sg, 1, mcnt, tid, wid);
            const float* gb = isH ? b_gh : b_gc;
            if (wid < 4) {
                int row = m0 + wid * 32 + lid;
                uint32_t rg[32];
#pragma unroll 1
                for (int cb = 0; cb < 128; cb += 32) {
                    TC_LD_X32(rg, tmem_base + cb);
                    TC_WAIT_LD();
#pragma unroll
                    for (int jj = 0; jj < 32; jj++) {
                        int gcol = n0 + cb + jj;
                        float v = __uint_as_float(rg[jj]) + gb[gcol & 255];
                        bf16 hi, lo; bsplit(v, &hi, &lo);
                        g_GhiT[(size_t)gcol * N_NODES + row] = hi;
                        g_GloT[(size_t)gcol * N_NODES + row] = lo;
                    }
                }
                TC_FENCE_BEFORE();
            }
            __syncthreads();
        }
        // z tiles (2 per CTA)
#pragma unroll 1
        for (int zi = 0; zi < 2; zi++) {
            int zt = bid + zi * 128;
            int mz = (zt >> 3) * 128, nz = (zt & 7) * 128;
            Seg sg[2];
            sg[0].Ahi = g_xhi + (size_t)mz * (T_STEPS * D_IN) + (size_t)t * D_IN;
            sg[0].Alo = g_xlo + (size_t)mz * (T_STEPS * D_IN) + (size_t)t * D_IN;
            sg[0].lda = T_STEPS * D_IN;
            sg[0].Bhi = g_kThi + (size_t)nz * D_IN;
            sg[0].Blo = g_kTlo + (size_t)nz * D_IN;
            sg[0].ldb = D_IN;
            sg[0].nchunk = 1; sg[0].ksec = 2; sg[0].use_alo = 1;
            sg[1].Ahi = hphi + (size_t)mz * H_DIM;
            sg[1].Alo = hplo + (size_t)mz * H_DIM;
            sg[1].lda = H_DIM;
            sg[1].Bhi = g_rkThi + (size_t)nz * H_DIM;
            sg[1].Blo = g_rkTlo + (size_t)nz * H_DIM;
            sg[1].ldb = H_DIM;
            sg[1].nchunk = 4; sg[1].ksec = 8; sg[1].use_alo = 1;
            tc_tile_run(ctrl, stage_u, tmem_base, sg, 2, mcnt, tid, wid);
            if (wid < 4) {
                int row = mz + wid * 32 + lid;
                uint32_t rg[32];
#pragma unroll 1
                for (int cb = 0; cb < 128; cb += 32) {
                    TC_LD_X32(rg, tmem_base + cb);
                    TC_WAIT_LD();
#pragma unroll
                    for (int jj = 0; jj < 32; jj++) {
                        int zc = nz + cb + jj;
                        g_z[(size_t)row * (4 * H_DIM) + zc] =
                            __uint_as_float(rg[jj]) + lstm_b[zc];
                    }
                }
                TC_FENCE_BEFORE();
            }
            __syncthreads();
        }
        gsync();

        // ---- PHASE B ----
        for (int idx = gt; idx < N_NODES * H_DIM; idx += gs) {
            int n = idx >> 8, hh = idx & 255;
            const float* zr = g_z + (size_t)n * (4 * H_DIM);
            float zi = __ldcg(zr + hh);
            float zf = __ldcg(zr + H_DIM + hh);
            float zg = __ldcg(zr + 2 * H_DIM + hh);
            float zo = __ldcg(zr + 3 * H_DIM + hh);
            float cp = __bfloat162float(__ldcg(cphi + idx)) +
                       __bfloat162float(__ldcg(cplo + idx));
            float c = sigmoidf_(zf) * cp + sigmoidf_(zi) * tanhf(zg);
            bsplit(c, &g_ccurhi[idx], &g_ccurlo[idx]);
            bsplit(sigmoidf_(zo) * tanhf(c), &g_hcurhi[idx], &g_hcurlo[idx]);
        }
        __syncthreads();
        {
            // big GEMM: 1-term Ahi@Ghi, K-chunks of 128. Measured sensitivity
            // (R14): HG err 1.1e-3 -> final +2e-7, so ~4e-3 HG err -> ~+1e-6.
            tc_big_run(ctrl, stage_u, tmem_base,
                       g_Ahi + (size_t)m0 * N_NODES,
                       g_GhiT + (size_t)n0 * N_NODES,
                       mcnt, tid, wid);
            if (wid < 4) {
                int row = m0 + wid * 32 + lid;
                uint32_t rg[32];
#pragma unroll 1
                for (int cb = 0; cb < 128; cb += 32) {
                    TC_LD_X32(rg, tmem_base + cb);
                    TC_WAIT_LD();
#pragma unroll
                    for (int jj = 0; jj < 32; jj++) {
                        float v = tanhf(__uint_as_float(rg[jj]));
                        bf16 hi, lo; bsplit(v, &hi, &lo);
                        size_t ix = (size_t)row * (2 * H_DIM) + n0 + cb + jj;
                        g_HGhi[ix] = hi; g_HGlo[ix] = lo;
                    }
                }
                TC_FENCE_BEFORE();
            }
            __syncthreads();
        }
        gsync();

        // ---- PHASE C ----
        {
            const bool isH = (bid < 64);
            int ci = isH ? bid : bid - 64;
            int mc = (ci >> 1) * 128, nc = (ci & 1) * 128;
            Seg sg[2];
            sg[0].Ahi = (isH ? g_hcurhi : g_ccurhi) + (size_t)mc * H_DIM;
            sg[0].Alo = (isH ? g_hcurlo : g_ccurlo) + (size_t)mc * H_DIM;
            sg[0].lda = H_DIM;
            sg[0].Bhi = (isH ? g_WhcThi : g_WccThi) + (size_t)nc * H_DIM;
            sg[0].Blo = (isH ? g_WhcTlo : g_WccTlo) + (size_t)nc * H_DIM;
            sg[0].ldb = H_DIM;
            sg[0].nchunk = 4; sg[0].ksec = 8; sg[0].use_alo = 1;
            sg[1].Ahi = g_HGhi + (size_t)mc * (2 * H_DIM) + (isH ? 0 : H_DIM);
            sg[1].Alo = g_HGlo + (size_t)mc * (2 * H_DIM) + (isH ? 0 : H_DIM);
            sg[1].lda = 2 * H_DIM;
            sg[1].Bhi = (isH ? g_WhpThi : g_WcpThi) + (size_t)nc * H_DIM;
            sg[1].Blo = (isH ? g_WhpTlo : g_WcpTlo) + (size_t)nc * H_DIM;
            sg[1].ldb = H_DIM;
            sg[1].nchunk = 4; sg[1].ksec = 8; sg[1].use_alo = 1;
            tc_tile_run(ctrl, stage_u, tmem_base, sg, 2, mcnt, tid, wid);
            const float* cbias = isH ? b_h : b_c;
            bf16* Sh = (isH ? g_hhi : g_chi) + (size_t)nxt * stateN;
            bf16* Sl = (isH ? g_hlo : g_clo) + (size_t)nxt * stateN;
            if (wid < 4) {
                int row = mc + wid * 32 + lid;
                uint32_t rg[32];
#pragma unroll 1
                for (int cb = 0; cb < 128; cb += 32) {
                    TC_LD_X32(rg, tmem_base + cb);
                    TC_WAIT_LD();
#pragma unroll
                    for (int jj = 0; jj < 32; jj++) {
                        int sc = nc + cb + jj;
                        float v = sigmoidf_(__uint_as_float(rg[jj]) + cbias[sc]);
                        bf16 hi, lo; bsplit(v, &hi, &lo);
                        size_t ix = (size_t)row * H_DIM + sc;
                        Sh[ix] = hi; Sl[ix] = lo;
                    }
                }
                TC_FENCE_BEFORE();
            }
            __syncthreads();
        }
        gsync();

#else   // ------------------- fp32 fallback path -------------------
        float* h_prev = g_h + (size_t)cur * stateN;
        float* c_prev = g_c + (size_t)cur * stateN;
        float* h_next = g_h + (size_t)nxt * stateN;
        float* c_next = g_c + (size_t)nxt * stateN;
        if (t > 0) {
            int warp = bid * (NT / 32) + wid;
            for (int r = warp; r < N_NODES; r += NB * (NT / 32)) {
                const float* hr = h_prev + (size_t)r * H_DIM;
                float s0 = 0.f, s1 = 0.f;
#pragma unroll
                for (int j = 0; j < 8; j++) {
                    int k = lid + 32 * j;
                    float hv = __ldcg(hr + k);
                    s0 = fmaf(hv, W_out[2 * k + 0], s0);
                    s1 = fmaf(hv, W_out[2 * k + 1], s1);
                }
#pragma unroll
                for (int o = 16; o > 0; o >>= 1) {
                    s0 += __shfl_down_sync(0xffffffffu, s0, o);
                    s1 += __shfl_down_sync(0xffffffffu, s1, o);
                }
                if (lid == 0) {
                    size_t base = (size_t)r * T_STEPS * P_OUT + (size_t)(t - 1) * P_OUT;
                    out[base + 0] = s0 + b_out[0];
                    out[base + 1] = s1 + b_out[1];
                }
            }
        }
#pragma unroll 1
        for (int tile = bid; tile < 384; tile += NB) {
            if (tile < 64) {
                int tm = (tile >> 1) * 128, tn = (tile & 1) * 128;
                gemm_tile(smB, g_G, 2 * H_DIM, h_prev, H_DIM, W_gh, H_DIM, H_DIM,
                          nullptr, 0, nullptr, 0, 0, b_gh, tm, tn, 0);
            } else if (tile < 128) {
                int tt = tile - 64;
                int tm = (tt >> 1) * 128, tn = (tt & 1) * 128;
                gemm_tile(smB, g_G + H_DIM, 2 * H_DIM, c_prev, H_DIM, W_gc, H_DIM, H_DIM,
                          nullptr, 0, nullptr, 0, 0, b_gc, tm, tn, 0);
            } else {
                int tz = tile - 128;
                int tm = (tz >> 3) * 128, tn = (tz & 7) * 128;
                gemm_tile(smB, g_z, 4 * H_DIM,
                          inputs + (size_t)t * D_IN, T_STEPS * D_IN, kernelW, 4 * H_DIM, D_IN,
                          h_prev, H_DIM, rkernel, 4 * H_DIM, H_DIM,
                          lstm_b, tm, tn, 0);
            }
        }
        gsync();
        for (int idx = gt; idx < N_NODES * H_DIM; idx += gs) {
            int n = idx >> 8, hh = idx & 255;
            const float* zr = g_z + (size_t)n * (4 * H_DIM);
            float zi = __ldcg(zr + hh);
            float zf = __ldcg(zr + H_DIM + hh);
            float zg = __ldcg(zr + 2 * H_DIM + hh);
            float zo = __ldcg(zr + 3 * H_DIM + hh);
            float c = sigmoidf_(zf) * __ldcg(c_prev + idx) + sigmoidf_(zi) * tanhf(zg);
            g_ccur[idx] = c;
            g_hcur[idx] = sigmoidf_(zo) * tanhf(c);
        }
        __syncthreads();
        gemm_tile(smB, g_HG, 2 * H_DIM, A, N_NODES, g_G, 2 * H_DIM, N_NODES,
                  nullptr, 0, nullptr, 0, 0, nullptr, m0, n0, 1);
        gsync();
        if (bid < 64) {
            int tm = (bid >> 1) * 128, tn = (bid & 1) * 128;
            gemm_tile(smB, h_next, H_DIM,
                      g_hcur, H_DIM, W_hc, H_DIM, H_DIM,
                      g_HG, 2 * H_DIM, W_hp, H_DIM, H_DIM,
                      b_h, tm, tn, 2);
        } else {
            int tt = bid - 64;
            int tm = (tt >> 1) * 128, tn = (tt & 1) * 128;
            gemm_tile(smB, c_next, H_DIM,
                      g_ccur, H_DIM, W_cc, H_DIM, H_DIM,
                      g_HG + H_DIM, 2 * H_DIM, W_cp, H_DIM, H_DIM,
                      b_c, tm, tn, 2);
        }
        gsync();
#endif
    }

    // final output row for t = T-1
    {
        int warp = bid * (NT / 32) + wid;
        const int fb = T_STEPS & 1;
        for (int r = warp; r < N_NODES; r += NB * (NT / 32)) {
            float s0 = 0.f, s1 = 0.f;
#pragma unroll
            for (int j = 0; j < 8; j++) {
                int k = lid + 32 * j;
#if HAS_TC
                size_t ix = (size_t)fb * stateN + (size_t)r * H_DIM + k;
                float hv = __bfloat162float(__ldcg(g_hhi + ix)) +
                           __bfloat162float(__ldcg(g_hlo + ix));
#else
                float hv = __ldcg(g_h + (size_t)fb * stateN + (size_t)r * H_DIM + k);
#endif
                s0 = fmaf(hv, W_out[2 * k + 0], s0);
                s1 = fmaf(hv, W_out[2 * k + 1], s1);
            }
#pragma unroll
            for (int o = 16; o > 0; o >>= 1) {
                s0 += __shfl_down_sync(0xffffffffu, s0, o);
                s1 += __shfl_down_sync(0xffffffffu, s1, o);
            }
            if (lid == 0) {
                size_t base = (size_t)r * T_STEPS * P_OUT + (size_t)(T_STEPS - 1) * P_OUT;
                out[base + 0] = s0 + b_out[0];
                out[base + 1] = s1 + b_out[1];
            }
        }
    }

#if HAS_TC
    __syncthreads();
    if (wid == 0) TC_DEALLOC(tmem_base, 512);
#endif
}

// ---------------- launch ----------------
extern "C" void kernel_launch(void* const* d_in, const int* in_sizes, int n_in,
                              void* d_out, int out_size)
{
    const float* inputs  = (const float*)d_in[0];
    const float* A       = (const float*)d_in[1];
    const float* kernelW = (const float*)d_in[2];
    const float* rkernel = (const float*)d_in[3];
    const float* lstm_b  = (const float*)d_in[4];
    const float* W_gh    = (const float*)d_in[5];
    const float* b_gh    = (const float*)d_in[6];
    const float* W_gc    = (const float*)d_in[7];
    const float* b_gc    = (const float*)d_in[8];
    const float* W_hc    = (const float*)d_in[9];
    const float* W_hp    = (const float*)d_in[10];
    const float* b_h     = (const float*)d_in[11];
    const float* W_cc    = (const float*)d_in[12];
    const float* W_cp    = (const float*)d_in[13];
    const float* b_c     = (const float*)d_in[14];
    const float* W_out   = (const float*)d_in[15];
    const float* b_out   = (const float*)d_in[16];
    float* out = (float*)d_out;

    cudaFuncSetAttribute(rgcn_persistent,
                         cudaFuncAttributeMaxDynamicSharedMemorySize, SMEM_DYN);
    rgcn_persistent<<<NB, NT, SMEM_DYN>>>(inputs, A, kernelW, rkernel, lstm_b,
                                          W_gh, b_gh, W_gc, b_gc,
                                          W_hc, W_hp, b_h, W_cc, W_cp, b_c,
                                          W_out, b_out, out);
}

// round 16
// speedup vs baseline: 2.2479x; 1.0566x over previous
#include <cuda_runtime.h>
#include <cuda_bf16.h>
#include <math.h>
#include <stdint.h>

#define N_NODES 4096
#define T_STEPS 365
#define D_IN    16
#define H_DIM   256
#define P_OUT   2
#define NB      128
#define NT      256

#if defined(__CUDA_ARCH__) && (defined(__CUDA_ARCH_FEAT_SM103_ALL) || defined(__CUDA_ARCH_FEAT_SM100_ALL))
#define HAS_TC 1
#else
#define HAS_TC 0
#endif

#define KC 64
#define NSTAGE 3
#define STAGE_BYTES 65536          // generic: AHI|ALO|BHI|BLO 16K each
#define OFF_AHI 0                  // 1-term: A-K0|A-K1|B-K0|B-K1 16K each
#define OFF_ALO 16384
#define OFF_BHI 32768
#define OFF_BLO 49152
#define SMEM_DYN (1024 + 1024 + NSTAGE * STAGE_BYTES)

typedef __nv_bfloat16 bf16;

// ---------------- device scratch (TC path) ----------------
__device__ __align__(128) bf16 g_hhi[2 * N_NODES * H_DIM];
__device__ __align__(128) bf16 g_hlo[2 * N_NODES * H_DIM];
__device__ __align__(128) bf16 g_chi[2 * N_NODES * H_DIM];
__device__ __align__(128) bf16 g_clo[2 * N_NODES * H_DIM];
__device__ __align__(128) bf16 g_HGhi[N_NODES * 2 * H_DIM];
__device__ __align__(128) bf16 g_hcurhi[N_NODES * H_DIM];
__device__ __align__(128) bf16 g_hcurlo[N_NODES * H_DIM];
__device__ __align__(128) bf16 g_ccurhi[N_NODES * H_DIM];
__device__ __align__(128) bf16 g_ccurlo[N_NODES * H_DIM];
__device__ __align__(128) bf16 g_GhiT[2 * H_DIM * N_NODES];
__device__ __align__(128) bf16 g_Ahi[(size_t)N_NODES * N_NODES];
__device__ __align__(128) bf16 g_Alo[(size_t)N_NODES * N_NODES];
__device__ __align__(128) bf16 g_xhi[(size_t)N_NODES * T_STEPS * D_IN];
__device__ __align__(128) bf16 g_xlo[(size_t)N_NODES * T_STEPS * D_IN];
__device__ __align__(128) bf16 g_rkThi[4 * H_DIM * H_DIM], g_rkTlo[4 * H_DIM * H_DIM];
__device__ __align__(128) bf16 g_kThi [4 * H_DIM * D_IN],  g_kTlo [4 * H_DIM * D_IN];
__device__ __align__(128) bf16 g_WghThi[H_DIM * H_DIM];
__device__ __align__(128) bf16 g_WgcThi[H_DIM * H_DIM];
__device__ __align__(128) bf16 g_WhcThi[H_DIM * H_DIM], g_WhcTlo[H_DIM * H_DIM];
__device__ __align__(128) bf16 g_WhpThi[H_DIM * H_DIM], g_WhpTlo[H_DIM * H_DIM];
__device__ __align__(128) bf16 g_WccThi[H_DIM * H_DIM], g_WccTlo[H_DIM * H_DIM];
__device__ __align__(128) bf16 g_WcpThi[H_DIM * H_DIM], g_WcpTlo[H_DIM * H_DIM];
__device__ float g_z[N_NODES * 4 * H_DIM];
// fallback (fp32) scratch
__device__ float g_h[2 * N_NODES * H_DIM];
__device__ float g_c[2 * N_NODES * H_DIM];
__device__ float g_G [N_NODES * 2 * H_DIM];
__device__ float g_HG[N_NODES * 2 * H_DIM];
__device__ float g_hcur[N_NODES * H_DIM];
__device__ float g_ccur[N_NODES * H_DIM];

// ---------------- helpers ----------------
__device__ __forceinline__ uint32_t smem_u32(const void* p) {
    uint32_t a;
    asm("{ .reg .u64 t; cvta.to.shared.u64 t, %1; cvt.u32.u64 %0, t; }" : "=r"(a) : "l"(p));
    return a;
}
#define SW128(o) ((o) ^ (((o) >> 3) & 0x70))
__device__ __forceinline__ float sigmoidf_(float x) { return 1.f / (1.f + expf(-x)); }
__device__ __forceinline__ void bsplit(float v, bf16* hi, bf16* lo) {
    bf16 h = __float2bfloat16(v);
    *hi = h;
    *lo = __float2bfloat16(v - __bfloat162float(h));
}

#if HAS_TC
__device__ __forceinline__ uint32_t elect_one() {
    uint32_t p;
    asm volatile("{ .reg .pred p; elect.sync _|p, 0xFFFFFFFF; selp.b32 %0, 1, 0, p; }" : "=r"(p));
    return p;
}
#define CP_ASYNC16(dst, src) \
    asm volatile("cp.async.cg.shared.global [%0], [%1], 16;" :: "r"(dst), "l"(src) : "memory")
#define CP_COMMIT()  asm volatile("cp.async.commit_group;" ::: "memory")
#define CP_WAIT0()   asm volatile("cp.async.wait_group 0;" ::: "memory")
#define CP_WAIT1()   asm volatile("cp.async.wait_group 1;" ::: "memory")
#define MBAR_INIT(a, c) \
    asm volatile("mbarrier.init.shared.b64 [%0], %1;" :: "r"(a), "r"(c) : "memory")
#define MBAR_WAIT(a, par) do { \
    uint32_t _m = (a), _p = (par), _d; \
    asm volatile("{ .reg .pred p; mbarrier.try_wait.parity.acquire.cta.shared::cta.b64 p, [%1], %2; selp.b32 %0,1,0,p; }" \
        : "=r"(_d) : "r"(_m), "r"(_p) : "memory"); \
    if (!_d) { \
        asm volatile("{ .reg .pred P1; WL_%=: mbarrier.try_wait.parity.acquire.cta.shared::cta.b64 P1, [%0], %1, 0x989680; @P1 bra.uni WD_%=; bra.uni WL_%=; WD_%=: }" \
            :: "r"(_m), "r"(_p) : "memory"); \
    } } while (0)
#define TC_ALLOC(sp, n)   asm volatile("tcgen05.alloc.cta_group::1.sync.aligned.shared::cta.b32 [%0], %1;" :: "r"(sp), "r"(n) : "memory")
#define TC_DEALLOC(t, n)  asm volatile("tcgen05.dealloc.cta_group::1.sync.aligned.b32 %0, %1;" :: "r"(t), "r"(n))
#define TC_COMMIT(mb)     asm volatile("tcgen05.commit.cta_group::1.mbarrier::arrive::one.shared::cluster.b64 [%0];" :: "r"(mb) : "memory")
#define TC_FENCE_AFTER()  asm volatile("tcgen05.fence::after_thread_sync;" ::: "memory")
#define TC_FENCE_BEFORE() asm volatile("tcgen05.fence::before_thread_sync;" ::: "memory")
#define TC_WAIT_LD()      asm volatile("tcgen05.wait::ld.sync.aligned;" ::: "memory")
#define FENCE_ASYNC()     asm volatile("fence.proxy.async.shared::cta;" ::: "memory")

static __device__ __forceinline__ uint64_t make_desc_k(uint32_t addr) {
    return ((uint64_t)2 << 61) | ((uint64_t)1 << 46) | ((uint64_t)64 << 32) |
           ((uint64_t)1 << 16) | ((uint64_t)(addr >> 4) & 0x3FFF);
}
// kind::f16, d=f32, a=bf16, b=bf16, K-major, N=128, M=128
#define MMA_IDESC ((1u<<4)|(1u<<7)|(1u<<10)|(16u<<17)|(8u<<24))
__device__ __forceinline__ void mma_ss(uint32_t d, uint64_t ad, uint64_t bd, bool acc) {
    uint32_t en = acc ? 1u : 0u;
    asm volatile(
        "{ .reg .pred p; setp.ne.u32 p, %5, 0;\n\t"
        "tcgen05.mma.cta_group::1.kind::f16 [%0], %1, %2, %3, {%4,%4,%4,%4}, p; }"
        :: "r"(d), "l"(ad), "l"(bd), "r"(MMA_IDESC), "r"(0u), "r"(en) : "memory");
}
#define TC_LD_X32(r, ta) \
    asm volatile("tcgen05.ld.sync.aligned.32x32b.x32.b32 " \
        "{%0,%1,%2,%3,%4,%5,%6,%7,%8,%9,%10,%11,%12,%13,%14,%15," \
        "%16,%17,%18,%19,%20,%21,%22,%23,%24,%25,%26,%27,%28,%29,%30,%31}, [%32];" \
        : "=r"((r)[0]),"=r"((r)[1]),"=r"((r)[2]),"=r"((r)[3]),"=r"((r)[4]),"=r"((r)[5]),"=r"((r)[6]),"=r"((r)[7]), \
          "=r"((r)[8]),"=r"((r)[9]),"=r"((r)[10]),"=r"((r)[11]),"=r"((r)[12]),"=r"((r)[13]),"=r"((r)[14]),"=r"((r)[15]), \
          "=r"((r)[16]),"=r"((r)[17]),"=r"((r)[18]),"=r"((r)[19]),"=r"((r)[20]),"=r"((r)[21]),"=r"((r)[22]),"=r"((r)[23]), \
          "=r"((r)[24]),"=r"((r)[25]),"=r"((r)[26]),"=r"((r)[27]),"=r"((r)[28]),"=r"((r)[29]),"=r"((r)[30]),"=r"((r)[31]) \
        : "r"(ta))

struct Seg {
    const bf16* Ahi; const bf16* Alo; int lda;
    const bf16* Bhi; const bf16* Blo; int ldb;
    int nchunk;
    int ksec;
    int use_alo;
};

__device__ __forceinline__ void seg_of(const Seg* segs, int c, int& si, int& kc) {
    if (c < segs[0].nchunk) { si = 0; kc = c * KC; }
    else                    { si = 1; kc = (c - segs[0].nchunk) * KC; }
}

__device__ __forceinline__ void load_chunk(uint32_t st, const Seg& sg, int kc, int tid) {
    const int ksec = sg.ksec;
    const int ua = sg.use_alo;
#pragma unroll 4
    for (int q = tid; q < 1024; q += NT) {
        int row = q >> 3, sc = q & 7;
        if (sc < ksec) {
            uint32_t d = SW128((uint32_t)(row * 128 + sc * 16));
            CP_ASYNC16(st + OFF_AHI + d, sg.Ahi + (size_t)row * sg.lda + kc + sc * 8);
            if (ua)
                CP_ASYNC16(st + OFF_ALO + d, sg.Alo + (size_t)row * sg.lda + kc + sc * 8);
            CP_ASYNC16(st + OFF_BHI + d, sg.Bhi + (size_t)row * sg.ldb + kc + sc * 8);
            CP_ASYNC16(st + OFF_BLO + d, sg.Blo + (size_t)row * sg.ldb + kc + sc * 8);
        }
    }
}

// ---- generic 3-stage pipelined tile ----
__device__ __noinline__ void tc_tile_run(uint32_t ctrl, const uint32_t* stage_u,
                                         uint32_t tmem, const Seg* segs, int nseg,
                                         int* mcnt, int tid, int wid)
{
    int total = segs[0].nchunk;
    if (nseg > 1) total += segs[1].nchunk;

    {
        int si, kc;
        seg_of(segs, 0, si, kc);
        load_chunk(stage_u[0], segs[si], kc, tid);
        CP_COMMIT();
        if (total > 1) {
            seg_of(segs, 1, si, kc);
            load_chunk(stage_u[1], segs[si], kc, tid);
            CP_COMMIT();
        }
    }

    for (int cc = 0; cc < total; ++cc) {
        const int s = cc % NSTAGE;
        int si, kc;
        seg_of(segs, cc, si, kc);
        const int nks = segs[si].ksec >> 1;
        if (cc + 1 < total) CP_WAIT1(); else CP_WAIT0();
        __syncthreads();
        if (wid == 0) {
            FENCE_ASYNC();
            if (elect_one()) {
                uint64_t aHi = make_desc_k(stage_u[s] + OFF_AHI);
                uint64_t bHi = make_desc_k(stage_u[s] + OFF_BHI);
                uint64_t bLo = make_desc_k(stage_u[s] + OFF_BLO);
                for (int ks = 0; ks < nks; ks++)
                    mma_ss(tmem, aHi + ks * 2, bHi + ks * 2, !(cc == 0 && ks == 0));
                for (int ks = 0; ks < nks; ks++)
                    mma_ss(tmem, aHi + ks * 2, bLo + ks * 2, true);
                if (segs[si].use_alo) {
                    uint64_t aLo = make_desc_k(stage_u[s] + OFF_ALO);
                    for (int ks = 0; ks < nks; ks++)
                        mma_ss(tmem, aLo + ks * 2, bHi + ks * 2, true);
                }
                TC_COMMIT(ctrl + 8 + s * 8);
            }
        }
        if (cc >= 1) {
            const int pw = (cc - 1) % NSTAGE;
            MBAR_WAIT(ctrl + 8 + pw * 8, mcnt[pw] & 1);
            mcnt[pw]++;
        }
        if (cc + 2 < total) {
            int si2, kc2;
            seg_of(segs, cc + 2, si2, kc2);
            load_chunk(stage_u[(cc + 2) % NSTAGE], segs[si2], kc2, tid);
            CP_COMMIT();
        }
    }
    {
        const int pw = (total - 1) % NSTAGE;
        MBAR_WAIT(ctrl + 8 + pw * 8, mcnt[pw] & 1);
        mcnt[pw]++;
    }
    TC_FENCE_AFTER();
}

// ---- 1-term runner (Ahi@Bhi), K-chunks of 128, arbitrary strides/total ----
// Stage: [0,16K) A Kblk0, [16K,32K) A Kblk1, [32K,48K) B Kblk0, [48K,64K) B Kblk1.
__device__ __forceinline__ void load_1t(uint32_t st, const bf16* Ab, int lda,
                                        const bf16* Bb, int ldb, int kc, int tid) {
#pragma unroll 8
    for (int q = tid; q < 2048; q += NT) {
        int row = q >> 4, sec = q & 15;
        int kb = sec >> 3, sc = sec & 7;
        uint32_t d = SW128((uint32_t)(row * 128 + sc * 16)) + kb * 16384;
        int ko = kc + kb * 64 + sc * 8;
        CP_ASYNC16(st + d,         Ab + (size_t)row * lda + ko);
        CP_ASYNC16(st + 32768 + d, Bb + (size_t)row * ldb + ko);
    }
}

__device__ __noinline__ void tc_1term_run(uint32_t ctrl, const uint32_t* stage_u,
                                          uint32_t tmem, const bf16* Ab, int lda,
                                          const bf16* Bb, int ldb, int total,
                                          int* mcnt, int tid, int wid)
{
    load_1t(stage_u[0], Ab, lda, Bb, ldb, 0, tid);
    CP_COMMIT();
    if (total > 1) {
        load_1t(stage_u[1], Ab, lda, Bb, ldb, 128, tid);
        CP_COMMIT();
    }

    for (int cc = 0; cc < total; ++cc) {
        const int s = cc % NSTAGE;
        if (cc + 1 < total) CP_WAIT1(); else CP_WAIT0();
        __syncthreads();
        if (wid == 0) {
            FENCE_ASYNC();
            if (elect_one()) {
#pragma unroll
                for (int kb = 0; kb < 2; kb++) {
                    uint64_t aD = make_desc_k(stage_u[s] + kb * 16384);
                    uint64_t bD = make_desc_k(stage_u[s] + 32768 + kb * 16384);
#pragma unroll
                    for (int ks = 0; ks < 4; ks++)
                        mma_ss(tmem, aD + ks * 2, bD + ks * 2,
                               !(cc == 0 && kb == 0 && ks == 0));
                }
                TC_COMMIT(ctrl + 8 + s * 8);
            }
        }
        if (cc >= 1) {
            const int pw = (cc - 1) % NSTAGE;
            MBAR_WAIT(ctrl + 8 + pw * 8, mcnt[pw] & 1);
            mcnt[pw]++;
        }
        if (cc + 2 < total) {
            load_1t(stage_u[(cc + 2) % NSTAGE], Ab, lda, Bb, ldb, (cc + 2) * 128, tid);
            CP_COMMIT();
        }
    }
    {
        const int pw = (total - 1) % NSTAGE;
        MBAR_WAIT(ctrl + 8 + pw * 8, mcnt[pw] & 1);
        mcnt[pw]++;
    }
    TC_FENCE_AFTER();
}
#endif // HAS_TC

// ---------------- grid barrier ----------------
__device__ unsigned g_count;
__device__ volatile unsigned g_gen;
__device__ __forceinline__ void gsync() {
    __threadfence();
    __syncthreads();
    if (threadIdx.x == 0) {
        unsigned gen = g_gen;
        if (atomicAdd(&g_count, 1u) == (unsigned)NB - 1u) {
            g_count = 0;
            __threadfence();
            g_gen = gen + 1u;
        } else {
            while (g_gen == gen) __nanosleep(64);
            __threadfence();
        }
    }
    __syncthreads();
}

// ---------------- fp32 fallback GEMM ----------------
struct SmemTiles {
    float As[8][132];
    float Bs[8][132];
};
__device__ __noinline__ void gemm_tile(
    SmemTiles* smB,
    float* __restrict__ C, int ldc,
    const float* __restrict__ A1, int lda1,
    const float* __restrict__ B1, int ldb1, int K1,
    const float* __restrict__ A2, int lda2,
    const float* __restrict__ B2, int ldb2, int K2,
    const float* __restrict__ bias, int m0, int n0, int act)
{
    const int tid = threadIdx.x;
    const int tx = tid & 15, ty = tid >> 4;
    const int arow = tid >> 1, acol = (tid & 1) * 4;
    const int brow = tid >> 5, bcol = (tid & 31) * 4;
    float acc[8][8];
#pragma unroll
    for (int i = 0; i < 8; i++)
#pragma unroll
        for (int j = 0; j < 8; j++) acc[i][j] = 0.f;
    int buf = 0;
    const int npass = A2 ? 2 : 1;
    for (int pass = 0; pass < npass; ++pass) {
        const float* A = pass ? A2 : A1;
        const float* B = pass ? B2 : B1;
        const int lda = pass ? lda2 : lda1;
        const int ldb = pass ? ldb2 : ldb1;
        const int K   = pass ? K2  : K1;
        float4 av = __ldcg((const float4*)(A + (size_t)(m0 + arow) * lda + acol));
        float4 bv = __ldcg((const float4*)(B + (size_t)(brow) * ldb + n0 + bcol));
        for (int k0 = 0; k0 < K; k0 += 8) {
            SmemTiles* sm = &smB[buf];
            sm->As[acol + 0][arow] = av.x;
            sm->As[acol + 1][arow] = av.y;
            sm->As[acol + 2][arow] = av.z;
            sm->As[acol + 3][arow] = av.w;
            *(float4*)&sm->Bs[brow][bcol] = bv;
            __syncthreads();
            if (k0 + 8 < K) {
                av = __ldcg((const float4*)(A + (size_t)(m0 + arow) * lda + k0 + 8 + acol));
                bv = __ldcg((const float4*)(B + (size_t)(k0 + 8 + brow) * ldb + n0 + bcol));
            }
#pragma unroll
            for (int k = 0; k < 8; k++) {
                float4 a0 = *(const float4*)&sm->As[k][ty * 8];
                float4 a1 = *(const float4*)&sm->As[k][ty * 8 + 4];
                float4 b0 = *(const float4*)&sm->Bs[k][tx * 8];
                float4 b1 = *(const float4*)&sm->Bs[k][tx * 8 + 4];
                float ar[8] = {a0.x, a0.y, a0.z, a0.w, a1.x, a1.y, a1.z, a1.w};
                float br[8] = {b0.x, b0.y, b0.z, b0.w, b1.x, b1.y, b1.z, b1.w};
#pragma unroll
                for (int i = 0; i < 8; i++)
#pragma unroll
                    for (int j = 0; j < 8; j++)
                        acc[i][j] = fmaf(ar[i], br[j], acc[i][j]);
            }
            buf ^= 1;
        }
    }
    float bv8[8];
#pragma unroll
    for (int j = 0; j < 8; j++) bv8[j] = bias ? bias[n0 + tx * 8 + j] : 0.f;
#pragma unroll
    for (int i = 0; i < 8; i++) {
        float r[8];
#pragma unroll
        for (int j = 0; j < 8; j++) {
            float v = acc[i][j] + bv8[j];
            if (act == 1)      v = tanhf(v);
            else if (act == 2) v = sigmoidf_(v);
            r[j] = v;
        }
        float* cp = C + (size_t)(m0 + ty * 8 + i) * ldc + n0 + tx * 8;
        *(float4*)(cp)     = make_float4(r[0], r[1], r[2], r[3]);
        *(float4*)(cp + 4) = make_float4(r[4], r[5], r[6], r[7]);
    }
}

// ---------------- persistent kernel ----------------
__global__ void __launch_bounds__(NT, 1) rgcn_persistent(
    const float* __restrict__ inputs, const float* __restrict__ A,
    const float* __restrict__ kernelW, const float* __restrict__ rkernel,
    const float* __restrict__ lstm_b,
    const float* __restrict__ W_gh, const float* __restrict__ b_gh,
    const float* __restrict__ W_gc, const float* __restrict__ b_gc,
    const float* __restrict__ W_hc, const float* __restrict__ W_hp,
    const float* __restrict__ b_h,
    const float* __restrict__ W_cc, const float* __restrict__ W_cp,
    const float* __restrict__ b_c,
    const float* __restrict__ W_out, const float* __restrict__ b_out,
    float* __restrict__ out)
{
    extern __shared__ char smraw[];
    const int bid = blockIdx.x;
    const int tid = threadIdx.x;
    const int wid = tid >> 5;
    const int lid = tid & 31;
    const size_t stateN = (size_t)N_NODES * H_DIM;
    const int gt = bid * NT + tid, gs = NB * NT;

    uint32_t sb_raw = smem_u32(smraw);
    uint32_t sb = (sb_raw + 1023u) & ~1023u;
    char* smb = smraw + (sb - sb_raw);
    SmemTiles* smB = (SmemTiles*)(smb + 1024);

#if HAS_TC
    uint32_t ctrl = sb;
    uint32_t stage_u[NSTAGE] = {sb + 1024, sb + 1024 + STAGE_BYTES,
                                sb + 1024 + 2 * STAGE_BYTES};
    int mcnt[NSTAGE] = {0, 0, 0};
    if (tid == 0) { MBAR_INIT(ctrl + 8, 1); MBAR_INIT(ctrl + 16, 1); MBAR_INIT(ctrl + 24, 1); }
    if (wid == 0) TC_ALLOC(ctrl, 512);
    __syncthreads();
    uint32_t tmem_base;
    asm volatile("ld.shared.b32 %0, [%1];" : "=r"(tmem_base) : "r"(ctrl));

    // ---- one-time init ----
    for (int i = gt; i < (int)stateN; i += gs) {
        g_hhi[i] = __float2bfloat16(0.f); g_hlo[i] = __float2bfloat16(0.f);
        g_chi[i] = __float2bfloat16(0.f); g_clo[i] = __float2bfloat16(0.f);
    }
    for (size_t i = (size_t)gt; i < (size_t)N_NODES * N_NODES; i += (size_t)gs)
        bsplit(A[i], &g_Ahi[i], &g_Alo[i]);
    for (size_t i = (size_t)gt; i < (size_t)N_NODES * T_STEPS * D_IN; i += (size_t)gs)
        bsplit(inputs[i], &g_xhi[i], &g_xlo[i]);
    for (int i = gt; i < 4 * H_DIM * H_DIM; i += gs) {
        int n = i >> 8, k = i & 255;
        bsplit(rkernel[k * (4 * H_DIM) + n], &g_rkThi[i], &g_rkTlo[i]);
    }
    for (int i = gt; i < 4 * H_DIM * D_IN; i += gs) {
        int n = i >> 4, k = i & 15;
        bsplit(kernelW[k * (4 * H_DIM) + n], &g_kThi[i], &g_kTlo[i]);
    }
    for (int i = gt; i < H_DIM * H_DIM; i += gs) {
        int n = i >> 8, k = i & 255;
        g_WghThi[i] = __float2bfloat16(W_gh[k * H_DIM + n]);
        g_WgcThi[i] = __float2bfloat16(W_gc[k * H_DIM + n]);
        bsplit(W_hc[k * H_DIM + n], &g_WhcThi[i], &g_WhcTlo[i]);
        bsplit(W_hp[k * H_DIM + n], &g_WhpThi[i], &g_WhpTlo[i]);
        bsplit(W_cc[k * H_DIM + n], &g_WccThi[i], &g_WccTlo[i]);
        bsplit(W_cp[k * H_DIM + n], &g_WcpThi[i], &g_WcpTlo[i]);
    }
#else
    for (int i = gt; i < (int)stateN; i += gs) { g_h[i] = 0.f; g_c[i] = 0.f; }
#endif
    gsync();

    const int m0 = (bid >> 2) * 128;
    const int n0 = (bid & 3) * 128;

    for (int t = 0; t < T_STEPS; ++t) {
        const int cur = t & 1, nxt = (t + 1) & 1;

#if HAS_TC
        const bf16* hphi = g_hhi + (size_t)cur * stateN;
        const bf16* hplo = g_hlo + (size_t)cur * stateN;
        const bf16* cphi = g_chi + (size_t)cur * stateN;
        const bf16* cplo = g_clo + (size_t)cur * stateN;

        if (t > 0) {
            int warp = bid * (NT / 32) + wid;
            for (int r = warp; r < N_NODES; r += NB * (NT / 32)) {
                float s0 = 0.f, s1 = 0.f;
#pragma unroll
                for (int j = 0; j < 8; j++) {
                    int k = lid + 32 * j;
                    size_t ix = (size_t)r * H_DIM + k;
                    float hv = __bfloat162float(__ldcg(hphi + ix)) +
                               __bfloat162float(__ldcg(hplo + ix));
                    s0 = fmaf(hv, W_out[2 * k + 0], s0);
                    s1 = fmaf(hv, W_out[2 * k + 1], s1);
                }
#pragma unroll
                for (int o = 16; o > 0; o >>= 1) {
                    s0 += __shfl_down_sync(0xffffffffu, s0, o);
                    s1 += __shfl_down_sync(0xffffffffu, s1, o);
                }
                if (lid == 0) {
                    size_t base = (size_t)r * T_STEPS * P_OUT + (size_t)(t - 1) * P_OUT;
                    out[base + 0] = s0 + b_out[0];
                    out[base + 1] = s1 + b_out[1];
                }
            }
        }

        // ---- PHASE A: G tile (1-term, KC=128) -> G^T hi ----
        {
            const bool isH = (n0 < 256);
            tc_1term_run(ctrl, stage_u, tmem_base,
                         (isH ? hphi : cphi) + (size_t)m0 * H_DIM, H_DIM,
                         (isH ? g_WghThi : g_WgcThi) + (size_t)(n0 & 255) * H_DIM, H_DIM,
                         2, mcnt, tid, wid);
            const float* gb = isH ? b_gh : b_gc;
            if (wid < 4) {
                int row = m0 + wid * 32 + lid;
                uint32_t rg[32];
#pragma unroll 1
                for (int cb = 0; cb < 128; cb += 32) {
                    TC_LD_X32(rg, tmem_base + cb);
                    TC_WAIT_LD();
#pragma unroll
                    for (int jj = 0; jj < 32; jj++) {
                        int gcol = n0 + cb + jj;
                        float v = __uint_as_float(rg[jj]) + gb[gcol & 255];
                        g_GhiT[(size_t)gcol * N_NODES + row] = __float2bfloat16(v);
                    }
                }
                TC_FENCE_BEFORE();
            }
            __syncthreads();
        }
        // z tiles (2 per CTA) — 3-term (state-critical)
#pragma unroll 1
        for (int zi = 0; zi < 2; zi++) {
            int zt = bid + zi * 128;
            int mz = (zt >> 3) * 128, nz = (zt & 7) * 128;
            Seg sg[2];
            sg[0].Ahi = g_xhi + (size_t)mz * (T_STEPS * D_IN) + (size_t)t * D_IN;
            sg[0].Alo = g_xlo + (size_t)mz * (T_STEPS * D_IN) + (size_t)t * D_IN;
            sg[0].lda = T_STEPS * D_IN;
            sg[0].Bhi = g_kThi + (size_t)nz * D_IN;
            sg[0].Blo = g_kTlo + (size_t)nz * D_IN;
            sg[0].ldb = D_IN;
            sg[0].nchunk = 1; sg[0].ksec = 2; sg[0].use_alo = 1;
            sg[1].Ahi = hphi + (size_t)mz * H_DIM;
            sg[1].Alo = hplo + (size_t)mz * H_DIM;
            sg[1].lda = H_DIM;
            sg[1].Bhi = g_rkThi + (size_t)nz * H_DIM;
            sg[1].Blo = g_rkTlo + (size_t)nz * H_DIM;
            sg[1].ldb = H_DIM;
            sg[1].nchunk = 4; sg[1].ksec = 8; sg[1].use_alo = 1;
            tc_tile_run(ctrl, stage_u, tmem_base, sg, 2, mcnt, tid, wid);
            if (wid < 4) {
                int row = mz + wid * 32 + lid;
                uint32_t rg[32];
#pragma unroll 1
                for (int cb = 0; cb < 128; cb += 32) {
                    TC_LD_X32(rg, tmem_base + cb);
                    TC_WAIT_LD();
#pragma unroll
                    for (int jj = 0; jj < 32; jj++) {
                        int zc = nz + cb + jj;
                        g_z[(size_t)row * (4 * H_DIM) + zc] =
                            __uint_as_float(rg[jj]) + lstm_b[zc];
                    }
                }
                TC_FENCE_BEFORE();
            }
            __syncthreads();
        }
        gsync();

        // ---- PHASE B ----
        for (int idx = gt; idx < N_NODES * H_DIM; idx += gs) {
            int n = idx >> 8, hh = idx & 255;
            const float* zr = g_z + (size_t)n * (4 * H_DIM);
            float zi = __ldcg(zr + hh);
            float zf = __ldcg(zr + H_DIM + hh);
            float zg = __ldcg(zr + 2 * H_DIM + hh);
            float zo = __ldcg(zr + 3 * H_DIM + hh);
            float cp = __bfloat162float(__ldcg(cphi + idx)) +
                       __bfloat162float(__ldcg(cplo + idx));
            float c = sigmoidf_(zf) * cp + sigmoidf_(zi) * tanhf(zg);
            bsplit(c, &g_ccurhi[idx], &g_ccurlo[idx]);
            bsplit(sigmoidf_(zo) * tanhf(c), &g_hcurhi[idx], &g_hcurlo[idx]);
        }
        __syncthreads();
        {
            // big GEMM: 1-term Ahi@Ghi, KC=128 (measured sensitivity: OK)
            tc_1term_run(ctrl, stage_u, tmem_base,
                         g_Ahi + (size_t)m0 * N_NODES, N_NODES,
                         g_GhiT + (size_t)n0 * N_NODES, N_NODES,
                         N_NODES / 128, mcnt, tid, wid);
            if (wid < 4) {
                int row = m0 + wid * 32 + lid;
                uint32_t rg[32];
#pragma unroll 1
                for (int cb = 0; cb < 128; cb += 32) {
                    TC_LD_X32(rg, tmem_base + cb);
                    TC_WAIT_LD();
#pragma unroll
                    for (int jj = 0; jj < 32; jj++) {
                        float v = tanhf(__uint_as_float(rg[jj]));
                        size_t ix = (size_t)row * (2 * H_DIM) + n0 + cb + jj;
                        g_HGhi[ix] = __float2bfloat16(v);
                    }
                }
                TC_FENCE_BEFORE();
            }
            __syncthreads();
        }
        gsync();

        // ---- PHASE C ----
        {
            const bool isH = (bid < 64);
            int ci = isH ? bid : bid - 64;
            int mc = (ci >> 1) * 128, nc = (ci & 1) * 128;
            Seg sg[2];
            sg[0].Ahi = (isH ? g_hcurhi : g_ccurhi) + (size_t)mc * H_DIM;
            sg[0].Alo = (isH ? g_hcurlo : g_ccurlo) + (size_t)mc * H_DIM;
            sg[0].lda = H_DIM;
            sg[0].Bhi = (isH ? g_WhcThi : g_WccThi) + (size_t)nc * H_DIM;
            sg[0].Blo = (isH ? g_WhcTlo : g_WccTlo) + (size_t)nc * H_DIM;
            sg[0].ldb = H_DIM;
            sg[0].nchunk = 4; sg[0].ksec = 8; sg[0].use_alo = 1;
            // HG operand 2-term: HGhi@(Whi+Wlo); HG already carries ~4e-3 err
            sg[1].Ahi = g_HGhi + (size_t)mc * (2 * H_DIM) + (isH ? 0 : H_DIM);
            sg[1].Alo = g_HGhi;   // unused (use_alo = 0)
            sg[1].lda = 2 * H_DIM;
            sg[1].Bhi = (isH ? g_WhpThi : g_WcpThi) + (size_t)nc * H_DIM;
            sg[1].Blo = (isH ? g_WhpTlo : g_WcpTlo) + (size_t)nc * H_DIM;
            sg[1].ldb = H_DIM;
            sg[1].nchunk = 4; sg[1].ksec = 8; sg[1].use_alo = 0;
            tc_tile_run(ctrl, stage_u, tmem_base, sg, 2, mcnt, tid, wid);
            const float* cbias = isH ? b_h : b_c;
            bf16* Sh = (isH ? g_hhi : g_chi) + (size_t)nxt * stateN;
            bf16* Sl = (isH ? g_hlo : g_clo) + (size_t)nxt * stateN;
            if (wid < 4) {
                int row = mc + wid * 32 + lid;
                uint32_t rg[32];
#pragma unroll 1
                for (int cb = 0; cb < 128; cb += 32) {
                    TC_LD_X32(rg, tmem_base + cb);
                    TC_WAIT_LD();
#pragma unroll
                    for (int jj = 0; jj < 32; jj++) {
                        int sc = nc + cb + jj;
                        float v = sigmoidf_(__uint_as_float(rg[jj]) + cbias[sc]);
                        bf16 hi, lo; bsplit(v, &hi, &lo);
                        size_t ix = (size_t)row * H_DIM + sc;
                        Sh[ix] = hi; Sl[ix] = lo;
                    }
                }
                TC_FENCE_BEFORE();
            }
            __syncthreads();
        }
        gsync();

#else   // ------------------- fp32 fallback path -------------------
        float* h_prev = g_h + (size_t)cur * stateN;
        float* c_prev = g_c + (size_t)cur * stateN;
        float* h_next = g_h + (size_t)nxt * stateN;
        float* c_next = g_c + (size_t)nxt * stateN;
        if (t > 0) {
            int warp = bid * (NT / 32) + wid;
            for (int r = warp; r < N_NODES; r += NB * (NT / 32)) {
                const float* hr = h_prev + (size_t)r * H_DIM;
                float s0 = 0.f, s1 = 0.f;
#pragma unroll
                for (int j = 0; j < 8; j++) {
                    int k = lid + 32 * j;
                    float hv = __ldcg(hr + k);
                    s0 = fmaf(hv, W_out[2 * k + 0], s0);
                    s1 = fmaf(hv, W_out[2 * k + 1], s1);
                }
#pragma unroll
                for (int o = 16; o > 0; o >>= 1) {
                    s0 += __shfl_down_sync(0xffffffffu, s0, o);
                    s1 += __shfl_down_sync(0xffffffffu, s1, o);
                }
                if (lid == 0) {
                    size_t base = (size_t)r * T_STEPS * P_OUT + (size_t)(t - 1) * P_OUT;
                    out[base + 0] = s0 + b_out[0];
                    out[base + 1] = s1 + b_out[1];
                }
            }
        }
#pragma unroll 1
        for (int tile = bid; tile < 384; tile += NB) {
            if (tile < 64) {
                int tm = (tile >> 1) * 128, tn = (tile & 1) * 128;
                gemm_tile(smB, g_G, 2 * H_DIM, h_prev, H_DIM, W_gh, H_DIM, H_DIM,
                          nullptr, 0, nullptr, 0, 0, b_gh, tm, tn, 0);
            } else if (tile < 128) {
                int tt = tile - 64;
                int tm = (tt >> 1) * 128, tn = (tt & 1) * 128;
                gemm_tile(smB, g_G + H_DIM, 2 * H_DIM, c_prev, H_DIM, W_gc, H_DIM, H_DIM,
                          nullptr, 0, nullptr, 0, 0, b_gc, tm, tn, 0);
            } else {
                int tz = tile - 128;
                int tm = (tz >> 3) * 128, tn = (tz & 7) * 128;
                gemm_tile(smB, g_z, 4 * H_DIM,
                          inputs + (size_t)t * D_IN, T_STEPS * D_IN, kernelW, 4 * H_DIM, D_IN,
                          h_prev, H_DIM, rkernel, 4 * H_DIM, H_DIM,
                          lstm_b, tm, tn, 0);
            }
        }
        gsync();
        for (int idx = gt; idx < N_NODES * H_DIM; idx += gs) {
            int n = idx >> 8, hh = idx & 255;
            const float* zr = g_z + (size_t)n * (4 * H_DIM);
            float zi = __ldcg(zr + hh);
            float zf = __ldcg(zr + H_DIM + hh);
            float zg = __ldcg(zr + 2 * H_DIM + hh);
            float zo = __ldcg(zr + 3 * H_DIM + hh);
            float c = sigmoidf_(zf) * __ldcg(c_prev + idx) + sigmoidf_(zi) * tanhf(zg);
            g_ccur[idx] = c;
            g_hcur[idx] = sigmoidf_(zo) * tanhf(c);
        }
        __syncthreads();
        gemm_tile(smB, g_HG, 2 * H_DIM, A, N_NODES, g_G, 2 * H_DIM, N_NODES,
                  nullptr, 0, nullptr, 0, 0, nullptr, m0, n0, 1);
        gsync();
        if (bid < 64) {
            int tm = (bid >> 1) * 128, tn = (bid & 1) * 128;
            gemm_tile(smB, h_next, H_DIM,
                      g_hcur, H_DIM, W_hc, H_DIM, H_DIM,
                      g_HG, 2 * H_DIM, W_hp, H_DIM, H_DIM,
                      b_h, tm, tn, 2);
        } else {
            int tt = bid - 64;
            int tm = (tt >> 1) * 128, tn = (tt & 1) * 128;
            gemm_tile(smB, c_next, H_DIM,
                      g_ccur, H_DIM, W_cc, H_DIM, H_DIM,
                      g_HG + H_DIM, 2 * H_DIM, W_cp, H_DIM, H_DIM,
                      b_c, tm, tn, 2);
        }
        gsync();
#endif
    }

    // final output row for t = T-1
    {
        int warp = bid * (NT / 32) + wid;
        const int fb = T_STEPS & 1;
        for (int r = warp; r < N_NODES; r += NB * (NT / 32)) {
            float s0 = 0.f, s1 = 0.f;
#pragma unroll
            for (int j = 0; j < 8; j++) {
                int k = lid + 32 * j;
#if HAS_TC
                size_t ix = (size_t)fb * stateN + (size_t)r * H_DIM + k;
                float hv = __bfloat162float(__ldcg(g_hhi + ix)) +
                           __bfloat162float(__ldcg(g_hlo + ix));
#else
                float hv = __ldcg(g_h + (size_t)fb * stateN + (size_t)r * H_DIM + k);
#endif
                s0 = fmaf(hv, W_out[2 * k + 0], s0);
                s1 = fmaf(hv, W_out[2 * k + 1], s1);
            }
#pragma unroll
            for (int o = 16; o > 0; o >>= 1) {
                s0 += __shfl_down_sync(0xffffffffu, s0, o);
                s1 += __shfl_down_sync(0xffffffffu, s1, o);
            }
            if (lid == 0) {
                size_t base = (size_t)r * T_STEPS * P_OUT + (size_t)(T_STEPS - 1) * P_OUT;
                out[base + 0] = s0 + b_out[0];
                out[base + 1] = s1 + b_out[1];
            }
        }
    }

#if HAS_TC
    __syncthreads();
    if (wid == 0) TC_DEALLOC(tmem_base, 512);
#endif
}

// ---------------- launch ----------------
extern "C" void kernel_launch(void* const* d_in, const int* in_sizes, int n_in,
                              void* d_out, int out_size)
{
    const float* inputs  = (const float*)d_in[0];
    const float* A       = (const float*)d_in[1];
    const float* kernelW = (const float*)d_in[2];
    const float* rkernel = (const float*)d_in[3];
    const float* lstm_b  = (const float*)d_in[4];
    const float* W_gh    = (const float*)d_in[5];
    const float* b_gh    = (const float*)d_in[6];
    const float* W_gc    = (const float*)d_in[7];
    const float* b_gc    = (const float*)d_in[8];
    const float* W_hc    = (const float*)d_in[9];
    const float* W_hp    = (const float*)d_in[10];
    const float* b_h     = (const float*)d_in[11];
    const float* W_cc    = (const float*)d_in[12];
    const float* W_cp    = (const float*)d_in[13];
    const float* b_c     = (const float*)d_in[14];
    const float* W_out   = (const float*)d_in[15];
    const float* b_out   = (const float*)d_in[16];
    float* out = (float*)d_out;

    cudaFuncSetAttribute(rgcn_persistent,
                         cudaFuncAttributeMaxDynamicSharedMemorySize, SMEM_DYN);
    rgcn_persistent<<<NB, NT, SMEM_DYN>>>(inputs, A, kernelW, rkernel, lstm_b,
                                          W_gh, b_gh, W_gc, b_gc,
                                          W_hc, W_hp, b_h, W_cc, W_cp, b_c,
                                          W_out, b_out, out);
}